// round 11
// baseline (speedup 1.0000x reference)
#include <cuda_runtime.h>
#include <cuda_fp16.h>
#include <math.h>
#include <stdint.h>

// Problem constants (fixed shapes)
#define NB 4
#define NT 2048
#define NH 16
#define NC 1024
#define HD 64
#define NM (NB*NT)         // 8192
#define N3C (3*NC)         // 3072

// ---------------- scratch ----------------------------------------------------
__device__ float  g_qkv[(size_t)NM * N3C];          // fp32 qkv
__device__ __half g_q[(size_t)NB * NH * NT * HD];   // rope(Q)*0.125, fp16 [B,H,T,D]
__device__ __half g_k[(size_t)NB * NH * NT * HD];   // rope(K), fp16 [B,H,T,D]
__device__ __half g_v[(size_t)NB * NH * NT * HD];   // V fp16, [B,H,D,T]
__device__ __half g_oh[(size_t)NM * NC];            // attn out fp16
__device__ __half g_xh[(size_t)NM * NC];            // x fp16
__device__ __half g_w1t[(size_t)N3C * NC];          // w_qkv^T fp16 [3072][1024]
__device__ __half g_w2t[(size_t)NC * NC];           // w_proj^T fp16

// ---------------- helpers ----------------------------------------------------
__device__ __forceinline__ uint32_t pack2(float lo, float hi) {
    __half2 h = __floats2half2_rn(lo, hi);
    return *reinterpret_cast<uint32_t*>(&h);
}

__device__ __forceinline__ void mma_fp16(float c[4],
                                         uint32_t a0, uint32_t a1, uint32_t a2, uint32_t a3,
                                         uint32_t b0, uint32_t b1) {
    asm volatile(
        "mma.sync.aligned.m16n8k16.row.col.f32.f16.f16.f32 "
        "{%0,%1,%2,%3}, {%4,%5,%6,%7}, {%8,%9}, {%0,%1,%2,%3};\n"
        : "+f"(c[0]), "+f"(c[1]), "+f"(c[2]), "+f"(c[3])
        : "r"(a0), "r"(a1), "r"(a2), "r"(a3), "r"(b0), "r"(b1));
}

__device__ __forceinline__ void ldm_x4(uint32_t& r0, uint32_t& r1,
                                       uint32_t& r2, uint32_t& r3, uint32_t addr) {
    asm volatile("ldmatrix.sync.aligned.m8n8.x4.shared.b16 {%0,%1,%2,%3}, [%4];"
                 : "=r"(r0), "=r"(r1), "=r"(r2), "=r"(r3) : "r"(addr));
}

__device__ __forceinline__ void cp16(uint32_t smem_addr, const void* gptr) {
    asm volatile("cp.async.cg.shared.global [%0], [%1], 16;\n"
                 :: "r"(smem_addr), "l"(gptr));
}
__device__ __forceinline__ void cp_commit() {
    asm volatile("cp.async.commit_group;\n");
}
template <int N>
__device__ __forceinline__ void cp_wait() {
    asm volatile("cp.async.wait_group %0;\n" :: "n"(N));
}
__device__ __forceinline__ uint32_t smem_u32(const void* p) {
    return (uint32_t)__cvta_generic_to_shared(p);
}

// ---------------- prep kernels -----------------------------------------------
__global__ __launch_bounds__(256) void round_half(const float* __restrict__ in,
                                                  __half* __restrict__ out) {
    const size_t i = ((size_t)blockIdx.x * 256 + threadIdx.x) * 4;
    float4 v = *(const float4*)(in + i);
    uint2 o;
    o.x = pack2(v.x, v.y);
    o.y = pack2(v.z, v.w);
    *(uint2*)(out + i) = o;
}

// transpose + round: in fp32 [R][Cc] -> out fp16 [Cc][R]
__global__ __launch_bounds__(256) void transpose_round_h(const float* __restrict__ in,
                                                         __half* __restrict__ out,
                                                         int R, int Cc) {
    __shared__ float t[32][33];
    const int c0 = blockIdx.x * 32, r0 = blockIdx.y * 32;
    const int tx = threadIdx.x & 31, ty = threadIdx.x >> 5;
#pragma unroll
    for (int i = 0; i < 32; i += 8)
        t[ty + i][tx] = in[(size_t)(r0 + ty + i) * Cc + c0 + tx];
    __syncthreads();
#pragma unroll
    for (int i = 0; i < 32; i += 8)
        out[(size_t)(c0 + ty + i) * R + r0 + tx] = __float2half_rn(t[tx][ty + i]);
}

// ---------------- fp16 GEMM: CTA 256x128, warp 64x64, 3-stage ----------------
// C[M,N] = A[M,K] @ Bt[N,K]^T + bias. 256 threads (8 warps: 4 M-groups x 2 N).
#define GST 72                      // halfs per smem row (36 words)
#define GA_B (256 * GST * 2)        // A tile bytes per stage = 36864
#define GB_B (128 * GST * 2)        // B tile bytes per stage = 18432
#define GSTB (GA_B + GB_B)          // stage bytes = 55296

__global__ __launch_bounds__(256) void gemm_fp16(
    const __half* __restrict__ A, const __half* __restrict__ Bt,
    const float* __restrict__ bias, float* __restrict__ C,
    int M, int N, int K)
{
    extern __shared__ uint32_t gsm[];

    const int bx = blockIdx.x, by = blockIdx.y;
    const int tid = threadIdx.x;
    const int lane = tid & 31, wid = tid >> 5;
    const int wm = (wid & 3) * 64;       // 4 warp-groups along M (256 rows)
    const int wn = (wid >> 2) * 64;      // 2 warp-groups along N (128 cols)

    const uint32_t smem_base = smem_u32(gsm);

    const int lr = lane & 7, ts = lane >> 3;
    // A tiles: (mlo,klo)(mhi,klo)(mlo,khi)(mhi,khi) -> a0..a3
    const uint32_t a_off = ((wm + (ts & 1) * 8 + lr) * GST + (ts >> 1) * 8) * 2;
    // B tiles: (nlo,klo)(nlo,khi)(nhi,klo)(nhi,khi) -> b0..b3
    const uint32_t b_off = ((wn + (ts >> 1) * 8 + lr) * GST + (ts & 1) * 8) * 2;

    const __half* Ab  = A  + (size_t)(by * 256) * K;
    const __half* Btb = Bt + (size_t)(bx * 128) * K;

    auto load_stage = [&](int k0, int st) {
        const uint32_t base = smem_base + (uint32_t)st * GSTB;
#pragma unroll
        for (int t = 0; t < 8; t++) {         // A: 256 rows x 64 halfs
            const int ci = tid + t * 256;     // 0..2047
            const int row = ci >> 3, cw = (ci & 7) * 8;
            cp16(base + (row * GST + cw) * 2,
                 Ab + (size_t)row * K + k0 + cw);
        }
#pragma unroll
        for (int t = 0; t < 4; t++) {         // B: 128 rows x 64 halfs
            const int ci = tid + t * 256;     // 0..1023
            const int row = ci >> 3, cw = (ci & 7) * 8;
            cp16(base + GA_B + (row * GST + cw) * 2,
                 Btb + (size_t)row * K + k0 + cw);
        }
    };

    float c[4][8][4];
#pragma unroll
    for (int mi = 0; mi < 4; mi++)
#pragma unroll
        for (int ni = 0; ni < 8; ni++)
#pragma unroll
            for (int j = 0; j < 4; j++) c[mi][ni][j] = 0.f;

    const int nsteps = K / 64;
    load_stage(0, 0);
    cp_commit();
    load_stage(64, 1);
    cp_commit();

    int stg = 0, nstg = 2;
    for (int s = 0; s < nsteps; s++) {
        if (s < nsteps - 1) cp_wait<1>(); else cp_wait<0>();
        __syncthreads();
        if (s + 2 < nsteps) load_stage((s + 2) * 64, nstg);
        cp_commit();

        const uint32_t sb = smem_base + (uint32_t)stg * GSTB;
        const uint32_t a_addr = sb + a_off;
        const uint32_t b_addr = sb + GA_B + b_off;

#pragma unroll
        for (int kk = 0; kk < 4; kk++) {         // 4 x k16
            uint32_t a[4][4];
#pragma unroll
            for (int mi = 0; mi < 4; mi++)
                ldm_x4(a[mi][0], a[mi][1], a[mi][2], a[mi][3],
                       a_addr + mi * (16 * GST * 2) + kk * 32);
#pragma unroll
            for (int p = 0; p < 4; p++) {
                uint32_t b0, b1, b2, b3;
                ldm_x4(b0, b1, b2, b3, b_addr + p * (16 * GST * 2) + kk * 32);
#pragma unroll
                for (int mi = 0; mi < 4; mi++) {
                    mma_fp16(c[mi][2 * p],     a[mi][0], a[mi][1], a[mi][2], a[mi][3], b0, b1);
                    mma_fp16(c[mi][2 * p + 1], a[mi][0], a[mi][1], a[mi][2], a[mi][3], b2, b3);
                }
            }
        }
        stg = (stg == 2) ? 0 : stg + 1;
        nstg = (nstg == 2) ? 0 : nstg + 1;
    }

    // epilogue: bias + fp32 store
    const int gg = lane >> 2, tt = lane & 3;
#pragma unroll
    for (int mi = 0; mi < 4; mi++) {
        const int r0 = by * 256 + wm + mi * 16 + gg;
#pragma unroll
        for (int ni = 0; ni < 8; ni++) {
            const int col = bx * 128 + wn + ni * 8 + 2 * tt;
            const float bz0 = bias[col], bz1 = bias[col + 1];
            *(float2*)(C + (size_t)r0 * N + col) =
                make_float2(c[mi][ni][0] + bz0, c[mi][ni][1] + bz1);
            *(float2*)(C + (size_t)(r0 + 8) * N + col) =
                make_float2(c[mi][ni][2] + bz0, c[mi][ni][3] + bz1);
        }
    }
}

// ---------------- RoPE + split Q/K into fp16 [B,H,T,D] -----------------------
// Q pre-scaled by 0.125 (exact power of two; folds attention scale away).
__global__ __launch_bounds__(256) void rope_split(void)
{
    const int p = blockIdx.x * blockDim.x + threadIdx.x;
    const int i   = p & 31;
    const int h   = (p >> 5) & 15;
    const int row = p >> 9;
    const int t   = row & (NT - 1);
    const int b   = row >> 11;

    const float inv_freq = __expf(-(float)(2 * i) * (9.210340371976184f / (float)HD));
    const float theta = (float)t * inv_freq;
    float sn, cs;
    sincosf(theta, &sn, &cs);

    const size_t base = (size_t)row * N3C + h * HD + 2 * i;
    const float q0 = g_qkv[base],      q1 = g_qkv[base + 1];
    const float k0 = g_qkv[base + NC], k1 = g_qkv[base + NC + 1];

    const size_t oidx = (((size_t)(b * NH + h) * NT + t) * HD) + 2 * i;
    *(uint32_t*)(g_q + oidx) = pack2((q0 * cs - q1 * sn) * 0.125f,
                                     (q1 * cs + q0 * sn) * 0.125f);
    *(uint32_t*)(g_k + oidx) = pack2(k0 * cs - k1 * sn,
                                     k1 * cs + k0 * sn);
}

// ---------------- V transpose: qkv[:, 2C + h*64 + d] -> g_v fp16 [B,H,D,T] ---
#define TS 67
__global__ __launch_bounds__(256) void transpose_v(void)
{
    __shared__ float Ts[64 * TS];
    const int t0 = blockIdx.x * 64;
    const int h  = blockIdx.y;
    const int b  = blockIdx.z;
    const int tid = threadIdx.x;

#pragma unroll
    for (int p = 0; p < 4; p++) {
        const int lin = tid + p * 256;
        const int trow = lin >> 4;
        const int c4 = (lin & 15) * 4;
        float4 v = *(const float4*)(g_qkv + (size_t)(b * NT + t0 + trow) * N3C
                                    + 2 * NC + h * HD + c4);
        Ts[trow * TS + c4 + 0] = v.x;
        Ts[trow * TS + c4 + 1] = v.y;
        Ts[trow * TS + c4 + 2] = v.z;
        Ts[trow * TS + c4 + 3] = v.w;
    }
    __syncthreads();

#pragma unroll
    for (int p = 0; p < 4; p++) {
        const int lin = tid + p * 256;
        const int d  = lin >> 4;
        const int t4 = (lin & 15) * 4;
        uint2 o;
        o.x = pack2(Ts[(t4 + 0) * TS + d], Ts[(t4 + 1) * TS + d]);
        o.y = pack2(Ts[(t4 + 2) * TS + d], Ts[(t4 + 3) * TS + d]);
        *(uint2*)(g_v + ((size_t)(b * NH + h) * HD + d) * NT + t0 + t4) = o;
    }
}

// ---------------- Flash attention: 128 thr, 4 warps (32 q rows each) ---------
// BQ=128, BKV=64. K/V duplication x4 (was x8). P: direct C->A half2 pack.
#define KOPB (64 * GST * 2)        // 9216 bytes (one 64-row tile)
#define FSTB (2 * KOPB)            // stage bytes = 18432 (K tile + V tile)

__global__ __launch_bounds__(128) void flash_fp16(void)
{
    extern __shared__ uint32_t fsm[];

    const int qt = blockIdx.x, h = blockIdx.y, b = blockIdx.z;
    const int t0 = qt * 128;
    const int tid = threadIdx.x;
    const int lane = tid & 31, wid = tid >> 5;
    const int g = lane >> 2, tg = lane & 3;
    const int qbase = wid * 32;          // 4 warps x 32 q rows

    const __half* Qb  = g_q + (size_t)(b * NH + h) * NT * HD;
    const __half* Kb  = g_k + (size_t)(b * NH + h) * NT * HD;
    const __half* Vtb = g_v + (size_t)(b * NH + h) * HD * NT;

    const uint32_t smem_base = smem_u32(fsm);

    const int lr = lane & 7, ts = lane >> 3;
    // A-style (Q): (mlo,klo)(mhi,klo)(mlo,khi)(mhi,khi)
    const uint32_t qa_off = ((qbase + (ts & 1) * 8 + lr) * GST + (ts >> 1) * 8) * 2;
    // B-style (K rows=kv, V rows=d): (nlo,klo)(nlo,khi)(nhi,klo)(nhi,khi)
    const uint32_t fb_off = (((ts >> 1) * 8 + lr) * GST + (ts & 1) * 8) * 2;

    // stage Q tile [128][64 halfs] into stage 0
#pragma unroll
    for (int t = 0; t < 8; t++) {
        const int ci = tid + t * 128;        // 0..1023
        const int row = ci >> 3, cw = (ci & 7) * 8;
        cp16(smem_base + (row * GST + cw) * 2,
             Qb + (size_t)(t0 + row) * HD + cw);
    }
    cp_commit();
    cp_wait<0>();
    __syncthreads();

    uint32_t qa[4][2][4];                    // [kk][mi][frag]
#pragma unroll
    for (int kk = 0; kk < 4; kk++)
#pragma unroll
        for (int mi = 0; mi < 2; mi++)
            ldm_x4(qa[kk][mi][0], qa[kk][mi][1], qa[kk][mi][2], qa[kk][mi][3],
                   smem_base + qa_off + mi * (16 * GST * 2) + kk * 32);
    __syncthreads();   // qa reads done before stage-0 overwrite

    auto load_tile = [&](int kt, int buf) {
        const uint32_t base = smem_base + (uint32_t)buf * FSTB;
#pragma unroll
        for (int t = 0; t < 4; t++) {
            const int ci = tid + t * 128;    // 0..511
            const int row = ci >> 3, cw = (ci & 7) * 8;
            cp16(base + (row * GST + cw) * 2,
                 Kb + (size_t)(kt * 64 + row) * HD + cw);
            cp16(base + KOPB + (row * GST + cw) * 2,
                 Vtb + (size_t)row * NT + kt * 64 + cw);
        }
    };

    float o[2][8][4];
#pragma unroll
    for (int mi = 0; mi < 2; mi++)
#pragma unroll
        for (int ni = 0; ni < 8; ni++)
#pragma unroll
            for (int j = 0; j < 4; j++) o[mi][ni][j] = 0.f;
    float mA[2] = {-INFINITY, -INFINITY}, mB[2] = {-INFINITY, -INFINITY};
    float lA[2] = {0.f, 0.f}, lB[2] = {0.f, 0.f};

    load_tile(0, 0);
    cp_commit();
    load_tile(1, 1);
    cp_commit();

    const int NITER = NT / 64;
    int stg = 0, nstg = 2;
    for (int kt = 0; kt < NITER; kt++) {
        if (kt < NITER - 1) cp_wait<1>(); else cp_wait<0>();
        __syncthreads();
        if (kt + 2 < NITER) load_tile(kt + 2, nstg);
        cp_commit();

        const uint32_t k_addr = smem_base + (uint32_t)stg * FSTB + fb_off;
        const uint32_t v_addr = k_addr + KOPB;

        // S = (Q*0.125) @ K^T   (warp: 32 q x 64 kv)
        float s[2][8][4];
#pragma unroll
        for (int mi = 0; mi < 2; mi++)
#pragma unroll
            for (int ni = 0; ni < 8; ni++)
#pragma unroll
                for (int j = 0; j < 4; j++) s[mi][ni][j] = 0.f;

#pragma unroll
        for (int kk = 0; kk < 4; kk++) {
#pragma unroll
            for (int p = 0; p < 4; p++) {
                uint32_t b0, b1, b2, b3;
                ldm_x4(b0, b1, b2, b3, k_addr + p * (16 * GST * 2) + kk * 32);
#pragma unroll
                for (int mi = 0; mi < 2; mi++) {
                    mma_fp16(s[mi][2 * p],     qa[kk][mi][0], qa[kk][mi][1],
                             qa[kk][mi][2], qa[kk][mi][3], b0, b1);
                    mma_fp16(s[mi][2 * p + 1], qa[kk][mi][0], qa[kk][mi][1],
                             qa[kk][mi][2], qa[kk][mi][3], b2, b3);
                }
            }
        }

        // online softmax per mi (rows qbase+mi*16+g and +8)
#pragma unroll
        for (int mi = 0; mi < 2; mi++) {
            float mx0 = -INFINITY, mx1 = -INFINITY;
#pragma unroll
            for (int ni = 0; ni < 8; ni++) {
                mx0 = fmaxf(mx0, fmaxf(s[mi][ni][0], s[mi][ni][1]));
                mx1 = fmaxf(mx1, fmaxf(s[mi][ni][2], s[mi][ni][3]));
            }
            mx0 = fmaxf(mx0, __shfl_xor_sync(0xffffffffu, mx0, 1));
            mx0 = fmaxf(mx0, __shfl_xor_sync(0xffffffffu, mx0, 2));
            mx1 = fmaxf(mx1, __shfl_xor_sync(0xffffffffu, mx1, 1));
            mx1 = fmaxf(mx1, __shfl_xor_sync(0xffffffffu, mx1, 2));

            const float mn0 = fmaxf(mA[mi], mx0);
            const float mn1 = fmaxf(mB[mi], mx1);
            const float al0 = __expf(mA[mi] - mn0);
            const float al1 = __expf(mB[mi] - mn1);
            mA[mi] = mn0; mB[mi] = mn1;

            float sum0 = 0.f, sum1 = 0.f;
#pragma unroll
            for (int ni = 0; ni < 8; ni++) {
                s[mi][ni][0] = __expf(s[mi][ni][0] - mn0);
                s[mi][ni][1] = __expf(s[mi][ni][1] - mn0);
                s[mi][ni][2] = __expf(s[mi][ni][2] - mn1);
                s[mi][ni][3] = __expf(s[mi][ni][3] - mn1);
                sum0 += s[mi][ni][0] + s[mi][ni][1];
                sum1 += s[mi][ni][2] + s[mi][ni][3];
                o[mi][ni][0] *= al0; o[mi][ni][1] *= al0;
                o[mi][ni][2] *= al1; o[mi][ni][3] *= al1;
            }
            sum0 += __shfl_xor_sync(0xffffffffu, sum0, 1);
            sum0 += __shfl_xor_sync(0xffffffffu, sum0, 2);
            sum1 += __shfl_xor_sync(0xffffffffu, sum1, 1);
            sum1 += __shfl_xor_sync(0xffffffffu, sum1, 2);
            lA[mi] = lA[mi] * al0 + sum0;
            lB[mi] = lB[mi] * al1 + sum1;
        }

        // O += P @ V : P C-frag packs directly into fp16 A-frag
#pragma unroll
        for (int kk = 0; kk < 4; kk++) {      // kv 16-chunks
            uint32_t pa[2][4];
#pragma unroll
            for (int mi = 0; mi < 2; mi++) {
                pa[mi][0] = pack2(s[mi][2 * kk][0],     s[mi][2 * kk][1]);
                pa[mi][1] = pack2(s[mi][2 * kk][2],     s[mi][2 * kk][3]);
                pa[mi][2] = pack2(s[mi][2 * kk + 1][0], s[mi][2 * kk + 1][1]);
                pa[mi][3] = pack2(s[mi][2 * kk + 1][2], s[mi][2 * kk + 1][3]);
            }
#pragma unroll
            for (int p = 0; p < 4; p++) {     // d 16-blocks
                uint32_t b0, b1, b2, b3;
                ldm_x4(b0, b1, b2, b3, v_addr + p * (16 * GST * 2) + kk * 32);
#pragma unroll
                for (int mi = 0; mi < 2; mi++) {
                    mma_fp16(o[mi][2 * p],     pa[mi][0], pa[mi][1], pa[mi][2], pa[mi][3], b0, b1);
                    mma_fp16(o[mi][2 * p + 1], pa[mi][0], pa[mi][1], pa[mi][2], pa[mi][3], b2, b3);
                }
            }
        }

        stg = (stg == 2) ? 0 : stg + 1;
        nstg = (nstg == 2) ? 0 : nstg + 1;
    }

    // epilogue: normalize, store fp16 to g_oh [B*T][C]
#pragma unroll
    for (int mi = 0; mi < 2; mi++) {
        const float inv0 = 1.0f / lA[mi];
        const float inv1 = 1.0f / lB[mi];
        const size_t r0 = (size_t)(b * NT + t0 + qbase + mi * 16 + g) * NC + h * HD;
        const size_t r1 = r0 + (size_t)8 * NC;
#pragma unroll
        for (int ni = 0; ni < 8; ni++) {
            const int col = ni * 8 + 2 * tg;
            *(uint32_t*)(g_oh + r0 + col) = pack2(o[mi][ni][0] * inv0, o[mi][ni][1] * inv0);
            *(uint32_t*)(g_oh + r1 + col) = pack2(o[mi][ni][2] * inv1, o[mi][ni][3] * inv1);
        }
    }
}

// ---------------- launch ------------------------------------------------------
extern "C" void kernel_launch(void* const* d_in, const int* in_sizes, int n_in,
                              void* d_out, int out_size)
{
    const float* x      = (const float*)d_in[0];
    const float* w_qkv  = (const float*)d_in[1];
    const float* b_qkv  = (const float*)d_in[2];
    const float* w_proj = (const float*)d_in[3];
    const float* b_proj = (const float*)d_in[4];
    float* out = (float*)d_out;

    float *p_qkv;
    __half *p_oh, *p_xh, *p_w1t, *p_w2t;
    cudaGetSymbolAddress((void**)&p_qkv, g_qkv);
    cudaGetSymbolAddress((void**)&p_oh,  g_oh);
    cudaGetSymbolAddress((void**)&p_xh,  g_xh);
    cudaGetSymbolAddress((void**)&p_w1t, g_w1t);
    cudaGetSymbolAddress((void**)&p_w2t, g_w2t);

    const int gemm_smem  = 3 * GSTB;     // 165888 B
    const int flash_smem = 3 * FSTB;     // 55296 B
    cudaFuncSetAttribute(gemm_fp16, cudaFuncAttributeMaxDynamicSharedMemorySize,
                         gemm_smem);
    cudaFuncSetAttribute(flash_fp16, cudaFuncAttributeMaxDynamicSharedMemorySize,
                         flash_smem);

    // 0) prep: x -> fp16; weights -> transposed fp16 [N][K]
    round_half<<<(NM * NC) / 1024, 256>>>(x, p_xh);
    {
        dim3 grid(N3C / 32, NC / 32);
        transpose_round_h<<<grid, 256>>>(w_qkv, p_w1t, NC, N3C);
    }
    {
        dim3 grid(NC / 32, NC / 32);
        transpose_round_h<<<grid, 256>>>(w_proj, p_w2t, NC, NC);
    }

    // 1) qkv = x @ w_qkv + b_qkv  (fp32 out)
    {
        dim3 grid(N3C / 128, NM / 256);
        gemm_fp16<<<grid, 256, gemm_smem>>>(p_xh, p_w1t, b_qkv, p_qkv, NM, N3C, NC);
    }
    // 2) rope Q,K -> fp16 [B,H,T,D] (Q pre-scaled by 1/8)
    {
        const int total_pairs = NM * NH * (HD / 2);
        rope_split<<<total_pairs / 256, 256>>>();
    }
    // 3) V -> fp16 [B,H,D,T]
    {
        dim3 grid(NT / 64, NH, NB);
        transpose_v<<<grid, 256>>>();
    }
    // 4) flash attention -> g_oh fp16
    {
        dim3 grid(NT / 128, NH, NB);
        flash_fp16<<<grid, 128, flash_smem>>>();
    }
    // 5) out = g_oh @ w_proj + b_proj
    {
        dim3 grid(NC / 128, NM / 256);
        gemm_fp16<<<grid, 256, gemm_smem>>>(p_oh, p_w2t, b_proj, out, NM, NC, NC);
    }
}

// round 12
// speedup vs baseline: 1.0670x; 1.0670x over previous
#include <cuda_runtime.h>
#include <cuda_fp16.h>
#include <math.h>
#include <stdint.h>

// Problem constants (fixed shapes)
#define NB 4
#define NT 2048
#define NH 16
#define NC 1024
#define HD 64
#define NM (NB*NT)         // 8192
#define N3C (3*NC)         // 3072

// ---------------- scratch ----------------------------------------------------
__device__ float  g_qkv[(size_t)NM * N3C];          // fp32 qkv
__device__ __half g_q[(size_t)NB * NH * NT * HD];   // rope(Q)*0.125, fp16 [B,H,T,D]
__device__ __half g_k[(size_t)NB * NH * NT * HD];   // rope(K), fp16 [B,H,T,D]
__device__ __half g_v[(size_t)NB * NH * NT * HD];   // V fp16, [B,H,D,T]
__device__ __half g_oh[(size_t)NM * NC];            // attn out fp16
__device__ __half g_xh[(size_t)NM * NC];            // x fp16
__device__ __half g_w1t[(size_t)N3C * NC];          // w_qkv^T fp16 [3072][1024]
__device__ __half g_w2t[(size_t)NC * NC];           // w_proj^T fp16

// ---------------- helpers ----------------------------------------------------
__device__ __forceinline__ uint32_t pack2(float lo, float hi) {
    __half2 h = __floats2half2_rn(lo, hi);
    return *reinterpret_cast<uint32_t*>(&h);
}

__device__ __forceinline__ void mma_fp16(float c[4],
                                         uint32_t a0, uint32_t a1, uint32_t a2, uint32_t a3,
                                         uint32_t b0, uint32_t b1) {
    asm volatile(
        "mma.sync.aligned.m16n8k16.row.col.f32.f16.f16.f32 "
        "{%0,%1,%2,%3}, {%4,%5,%6,%7}, {%8,%9}, {%0,%1,%2,%3};\n"
        : "+f"(c[0]), "+f"(c[1]), "+f"(c[2]), "+f"(c[3])
        : "r"(a0), "r"(a1), "r"(a2), "r"(a3), "r"(b0), "r"(b1));
}

__device__ __forceinline__ void ldm_x4(uint32_t& r0, uint32_t& r1,
                                       uint32_t& r2, uint32_t& r3, uint32_t addr) {
    asm volatile("ldmatrix.sync.aligned.m8n8.x4.shared.b16 {%0,%1,%2,%3}, [%4];"
                 : "=r"(r0), "=r"(r1), "=r"(r2), "=r"(r3) : "r"(addr));
}

__device__ __forceinline__ void cp16(uint32_t smem_addr, const void* gptr) {
    asm volatile("cp.async.cg.shared.global [%0], [%1], 16;\n"
                 :: "r"(smem_addr), "l"(gptr));
}
__device__ __forceinline__ void cp_commit() {
    asm volatile("cp.async.commit_group;\n");
}
template <int N>
__device__ __forceinline__ void cp_wait() {
    asm volatile("cp.async.wait_group %0;\n" :: "n"(N));
}
__device__ __forceinline__ uint32_t smem_u32(const void* p) {
    return (uint32_t)__cvta_generic_to_shared(p);
}

// ---------------- prep kernels -----------------------------------------------
__global__ __launch_bounds__(256) void round_half(const float* __restrict__ in,
                                                  __half* __restrict__ out) {
    const size_t i = ((size_t)blockIdx.x * 256 + threadIdx.x) * 4;
    float4 v = *(const float4*)(in + i);
    uint2 o;
    o.x = pack2(v.x, v.y);
    o.y = pack2(v.z, v.w);
    *(uint2*)(out + i) = o;
}

// transpose + round: in fp32 [R][Cc] -> out fp16 [Cc][R]
__global__ __launch_bounds__(256) void transpose_round_h(const float* __restrict__ in,
                                                         __half* __restrict__ out,
                                                         int R, int Cc) {
    __shared__ float t[32][33];
    const int c0 = blockIdx.x * 32, r0 = blockIdx.y * 32;
    const int tx = threadIdx.x & 31, ty = threadIdx.x >> 5;
#pragma unroll
    for (int i = 0; i < 32; i += 8)
        t[ty + i][tx] = in[(size_t)(r0 + ty + i) * Cc + c0 + tx];
    __syncthreads();
#pragma unroll
    for (int i = 0; i < 32; i += 8)
        out[(size_t)(c0 + ty + i) * R + r0 + tx] = __float2half_rn(t[tx][ty + i]);
}

// ---------------- fp16 GEMM: CTA 128x128, warp 32x64, 3-stage ----------------
// C[M,N] = A[M,K] @ Bt[N,K]^T + bias. 256 threads (8 warps: 4 M x 2 N).
#define GST 72                      // halfs per smem row (36 words)
#define GOPB (128 * GST * 2)        // bytes per operand per stage = 18432
#define GSTB (2 * GOPB)             // stage bytes = 36864

__global__ __launch_bounds__(256) void gemm_fp16(
    const __half* __restrict__ A, const __half* __restrict__ Bt,
    const float* __restrict__ bias, float* __restrict__ C,
    int M, int N, int K)
{
    extern __shared__ uint32_t gsm[];

    const int bx = blockIdx.x, by = blockIdx.y;
    const int tid = threadIdx.x;
    const int lane = tid & 31, wid = tid >> 5;
    const int wm = (wid & 3) * 32;
    const int wn = (wid >> 2) * 64;

    const uint32_t smem_base = smem_u32(gsm);

    const int lr = lane & 7, ts = lane >> 3;
    // A tiles: (mlo,klo)(mhi,klo)(mlo,khi)(mhi,khi) -> a0..a3
    const uint32_t a_off = ((wm + (ts & 1) * 8 + lr) * GST + (ts >> 1) * 8) * 2;
    // B tiles: (nlo,klo)(nlo,khi)(nhi,klo)(nhi,khi) -> b0..b3
    const uint32_t b_off = ((wn + (ts >> 1) * 8 + lr) * GST + (ts & 1) * 8) * 2;

    const __half* Ab  = A  + (size_t)(by * 128) * K;
    const __half* Btb = Bt + (size_t)(bx * 128) * K;

    auto load_stage = [&](int k0, int st) {
        const uint32_t base = smem_base + (uint32_t)st * GSTB;
#pragma unroll
        for (int t = 0; t < 4; t++) {
            const int ci = tid + t * 256;          // 0..1023
            const int row = ci >> 3, cw = (ci & 7) * 8;   // halfs
            cp16(base + (row * GST + cw) * 2,
                 Ab + (size_t)row * K + k0 + cw);
            cp16(base + GOPB + (row * GST + cw) * 2,
                 Btb + (size_t)row * K + k0 + cw);
        }
    };

    float c[2][8][4];
#pragma unroll
    for (int mi = 0; mi < 2; mi++)
#pragma unroll
        for (int ni = 0; ni < 8; ni++)
#pragma unroll
            for (int j = 0; j < 4; j++) c[mi][ni][j] = 0.f;

    const int nsteps = K / 64;
    load_stage(0, 0);
    cp_commit();
    load_stage(64, 1);
    cp_commit();

    int stg = 0, nstg = 2;
    for (int s = 0; s < nsteps; s++) {
        if (s < nsteps - 1) cp_wait<1>(); else cp_wait<0>();
        __syncthreads();
        if (s + 2 < nsteps) load_stage((s + 2) * 64, nstg);
        cp_commit();

        const uint32_t sb = smem_base + (uint32_t)stg * GSTB;
        const uint32_t a_addr = sb + a_off;
        const uint32_t b_addr = sb + GOPB + b_off;

#pragma unroll
        for (int kk = 0; kk < 4; kk++) {         // 4 x k16
            uint32_t a[2][4];
#pragma unroll
            for (int mi = 0; mi < 2; mi++)
                ldm_x4(a[mi][0], a[mi][1], a[mi][2], a[mi][3],
                       a_addr + mi * (16 * GST * 2) + kk * 32);
#pragma unroll
            for (int p = 0; p < 4; p++) {
                uint32_t b0, b1, b2, b3;
                ldm_x4(b0, b1, b2, b3, b_addr + p * (16 * GST * 2) + kk * 32);
                mma_fp16(c[0][2 * p],     a[0][0], a[0][1], a[0][2], a[0][3], b0, b1);
                mma_fp16(c[0][2 * p + 1], a[0][0], a[0][1], a[0][2], a[0][3], b2, b3);
                mma_fp16(c[1][2 * p],     a[1][0], a[1][1], a[1][2], a[1][3], b0, b1);
                mma_fp16(c[1][2 * p + 1], a[1][0], a[1][1], a[1][2], a[1][3], b2, b3);
            }
        }
        stg = (stg == 2) ? 0 : stg + 1;
        nstg = (nstg == 2) ? 0 : nstg + 1;
    }

    // epilogue: bias + fp32 store
    const int gg = lane >> 2, tt = lane & 3;
#pragma unroll
    for (int mi = 0; mi < 2; mi++) {
        const int r0 = by * 128 + wm + mi * 16 + gg;
#pragma unroll
        for (int ni = 0; ni < 8; ni++) {
            const int col = bx * 128 + wn + ni * 8 + 2 * tt;
            const float bz0 = bias[col], bz1 = bias[col + 1];
            *(float2*)(C + (size_t)r0 * N + col) =
                make_float2(c[mi][ni][0] + bz0, c[mi][ni][1] + bz1);
            *(float2*)(C + (size_t)(r0 + 8) * N + col) =
                make_float2(c[mi][ni][2] + bz0, c[mi][ni][3] + bz1);
        }
    }
}

// ---------------- RoPE + split Q/K into fp16 [B,H,T,D] -----------------------
// Q pre-scaled by 0.125 (exact power of two; folds attention scale away).
__global__ __launch_bounds__(256) void rope_split(void)
{
    const int p = blockIdx.x * blockDim.x + threadIdx.x;
    const int i   = p & 31;
    const int h   = (p >> 5) & 15;
    const int row = p >> 9;
    const int t   = row & (NT - 1);
    const int b   = row >> 11;

    const float inv_freq = __expf(-(float)(2 * i) * (9.210340371976184f / (float)HD));
    const float theta = (float)t * inv_freq;
    float sn, cs;
    sincosf(theta, &sn, &cs);

    const size_t base = (size_t)row * N3C + h * HD + 2 * i;
    const float q0 = g_qkv[base],      q1 = g_qkv[base + 1];
    const float k0 = g_qkv[base + NC], k1 = g_qkv[base + NC + 1];

    const size_t oidx = (((size_t)(b * NH + h) * NT + t) * HD) + 2 * i;
    *(uint32_t*)(g_q + oidx) = pack2((q0 * cs - q1 * sn) * 0.125f,
                                     (q1 * cs + q0 * sn) * 0.125f);
    *(uint32_t*)(g_k + oidx) = pack2(k0 * cs - k1 * sn,
                                     k1 * cs + k0 * sn);
}

// ---------------- V transpose: qkv[:, 2C + h*64 + d] -> g_v fp16 [B,H,D,T] ---
#define TS 67
__global__ __launch_bounds__(256) void transpose_v(void)
{
    __shared__ float Ts[64 * TS];
    const int t0 = blockIdx.x * 64;
    const int h  = blockIdx.y;
    const int b  = blockIdx.z;
    const int tid = threadIdx.x;

#pragma unroll
    for (int p = 0; p < 4; p++) {
        const int lin = tid + p * 256;
        const int trow = lin >> 4;
        const int c4 = (lin & 15) * 4;
        float4 v = *(const float4*)(g_qkv + (size_t)(b * NT + t0 + trow) * N3C
                                    + 2 * NC + h * HD + c4);
        Ts[trow * TS + c4 + 0] = v.x;
        Ts[trow * TS + c4 + 1] = v.y;
        Ts[trow * TS + c4 + 2] = v.z;
        Ts[trow * TS + c4 + 3] = v.w;
    }
    __syncthreads();

#pragma unroll
    for (int p = 0; p < 4; p++) {
        const int lin = tid + p * 256;
        const int d  = lin >> 4;
        const int t4 = (lin & 15) * 4;
        uint2 o;
        o.x = pack2(Ts[(t4 + 0) * TS + d], Ts[(t4 + 1) * TS + d]);
        o.y = pack2(Ts[(t4 + 2) * TS + d], Ts[(t4 + 3) * TS + d]);
        *(uint2*)(g_v + ((size_t)(b * NH + h) * HD + d) * NT + t0 + t4) = o;
    }
}

// ---------------- Flash attention: 128 thr, 4 warps (32 q rows each) ---------
// BQ=128, BKV=64. K/V duplication x4. P: direct C->A half2 pack.
#define KOPB (64 * GST * 2)        // 9216 bytes (one 64-row tile)
#define FSTB (2 * KOPB)            // stage bytes = 18432 (K tile + V tile)

__global__ __launch_bounds__(128) void flash_fp16(void)
{
    extern __shared__ uint32_t fsm[];

    const int qt = blockIdx.x, h = blockIdx.y, b = blockIdx.z;
    const int t0 = qt * 128;
    const int tid = threadIdx.x;
    const int lane = tid & 31, wid = tid >> 5;
    const int g = lane >> 2, tg = lane & 3;
    const int qbase = wid * 32;          // 4 warps x 32 q rows

    const __half* Qb  = g_q + (size_t)(b * NH + h) * NT * HD;
    const __half* Kb  = g_k + (size_t)(b * NH + h) * NT * HD;
    const __half* Vtb = g_v + (size_t)(b * NH + h) * HD * NT;

    const uint32_t smem_base = smem_u32(fsm);

    const int lr = lane & 7, ts = lane >> 3;
    // A-style (Q): (mlo,klo)(mhi,klo)(mlo,khi)(mhi,khi)
    const uint32_t qa_off = ((qbase + (ts & 1) * 8 + lr) * GST + (ts >> 1) * 8) * 2;
    // B-style (K rows=kv, V rows=d): (nlo,klo)(nlo,khi)(nhi,klo)(nhi,khi)
    const uint32_t fb_off = (((ts >> 1) * 8 + lr) * GST + (ts & 1) * 8) * 2;

    // stage Q tile [128][64 halfs] into stage 0
#pragma unroll
    for (int t = 0; t < 8; t++) {
        const int ci = tid + t * 128;        // 0..1023
        const int row = ci >> 3, cw = (ci & 7) * 8;
        cp16(smem_base + (row * GST + cw) * 2,
             Qb + (size_t)(t0 + row) * HD + cw);
    }
    cp_commit();
    cp_wait<0>();
    __syncthreads();

    uint32_t qa[4][2][4];                    // [kk][mi][frag]
#pragma unroll
    for (int kk = 0; kk < 4; kk++)
#pragma unroll
        for (int mi = 0; mi < 2; mi++)
            ldm_x4(qa[kk][mi][0], qa[kk][mi][1], qa[kk][mi][2], qa[kk][mi][3],
                   smem_base + qa_off + mi * (16 * GST * 2) + kk * 32);
    __syncthreads();   // qa reads done before stage-0 overwrite

    auto load_tile = [&](int kt, int buf) {
        const uint32_t base = smem_base + (uint32_t)buf * FSTB;
#pragma unroll
        for (int t = 0; t < 4; t++) {
            const int ci = tid + t * 128;    // 0..511
            const int row = ci >> 3, cw = (ci & 7) * 8;
            cp16(base + (row * GST + cw) * 2,
                 Kb + (size_t)(kt * 64 + row) * HD + cw);
            cp16(base + KOPB + (row * GST + cw) * 2,
                 Vtb + (size_t)row * NT + kt * 64 + cw);
        }
    };

    float o[2][8][4];
#pragma unroll
    for (int mi = 0; mi < 2; mi++)
#pragma unroll
        for (int ni = 0; ni < 8; ni++)
#pragma unroll
            for (int j = 0; j < 4; j++) o[mi][ni][j] = 0.f;
    float mA[2] = {-INFINITY, -INFINITY}, mB[2] = {-INFINITY, -INFINITY};
    float lA[2] = {0.f, 0.f}, lB[2] = {0.f, 0.f};

    load_tile(0, 0);
    cp_commit();
    load_tile(1, 1);
    cp_commit();

    const int NITER = NT / 64;
    int stg = 0, nstg = 2;
    for (int kt = 0; kt < NITER; kt++) {
        if (kt < NITER - 1) cp_wait<1>(); else cp_wait<0>();
        __syncthreads();
        if (kt + 2 < NITER) load_tile(kt + 2, nstg);
        cp_commit();

        const uint32_t k_addr = smem_base + (uint32_t)stg * FSTB + fb_off;
        const uint32_t v_addr = k_addr + KOPB;

        // S = (Q*0.125) @ K^T   (warp: 32 q x 64 kv)
        float s[2][8][4];
#pragma unroll
        for (int mi = 0; mi < 2; mi++)
#pragma unroll
            for (int ni = 0; ni < 8; ni++)
#pragma unroll
                for (int j = 0; j < 4; j++) s[mi][ni][j] = 0.f;

#pragma unroll
        for (int kk = 0; kk < 4; kk++) {
#pragma unroll
            for (int p = 0; p < 4; p++) {
                uint32_t b0, b1, b2, b3;
                ldm_x4(b0, b1, b2, b3, k_addr + p * (16 * GST * 2) + kk * 32);
#pragma unroll
                for (int mi = 0; mi < 2; mi++) {
                    mma_fp16(s[mi][2 * p],     qa[kk][mi][0], qa[kk][mi][1],
                             qa[kk][mi][2], qa[kk][mi][3], b0, b1);
                    mma_fp16(s[mi][2 * p + 1], qa[kk][mi][0], qa[kk][mi][1],
                             qa[kk][mi][2], qa[kk][mi][3], b2, b3);
                }
            }
        }

        // online softmax per mi (rows qbase+mi*16+g and +8)
#pragma unroll
        for (int mi = 0; mi < 2; mi++) {
            float mx0 = -INFINITY, mx1 = -INFINITY;
#pragma unroll
            for (int ni = 0; ni < 8; ni++) {
                mx0 = fmaxf(mx0, fmaxf(s[mi][ni][0], s[mi][ni][1]));
                mx1 = fmaxf(mx1, fmaxf(s[mi][ni][2], s[mi][ni][3]));
            }
            mx0 = fmaxf(mx0, __shfl_xor_sync(0xffffffffu, mx0, 1));
            mx0 = fmaxf(mx0, __shfl_xor_sync(0xffffffffu, mx0, 2));
            mx1 = fmaxf(mx1, __shfl_xor_sync(0xffffffffu, mx1, 1));
            mx1 = fmaxf(mx1, __shfl_xor_sync(0xffffffffu, mx1, 2));

            const float mn0 = fmaxf(mA[mi], mx0);
            const float mn1 = fmaxf(mB[mi], mx1);
            const float al0 = __expf(mA[mi] - mn0);
            const float al1 = __expf(mB[mi] - mn1);
            mA[mi] = mn0; mB[mi] = mn1;

            float sum0 = 0.f, sum1 = 0.f;
#pragma unroll
            for (int ni = 0; ni < 8; ni++) {
                s[mi][ni][0] = __expf(s[mi][ni][0] - mn0);
                s[mi][ni][1] = __expf(s[mi][ni][1] - mn0);
                s[mi][ni][2] = __expf(s[mi][ni][2] - mn1);
                s[mi][ni][3] = __expf(s[mi][ni][3] - mn1);
                sum0 += s[mi][ni][0] + s[mi][ni][1];
                sum1 += s[mi][ni][2] + s[mi][ni][3];
                o[mi][ni][0] *= al0; o[mi][ni][1] *= al0;
                o[mi][ni][2] *= al1; o[mi][ni][3] *= al1;
            }
            sum0 += __shfl_xor_sync(0xffffffffu, sum0, 1);
            sum0 += __shfl_xor_sync(0xffffffffu, sum0, 2);
            sum1 += __shfl_xor_sync(0xffffffffu, sum1, 1);
            sum1 += __shfl_xor_sync(0xffffffffu, sum1, 2);
            lA[mi] = lA[mi] * al0 + sum0;
            lB[mi] = lB[mi] * al1 + sum1;
        }

        // O += P @ V : P C-frag packs directly into fp16 A-frag
#pragma unroll
        for (int kk = 0; kk < 4; kk++) {      // kv 16-chunks
            uint32_t pa[2][4];
#pragma unroll
            for (int mi = 0; mi < 2; mi++) {
                pa[mi][0] = pack2(s[mi][2 * kk][0],     s[mi][2 * kk][1]);
                pa[mi][1] = pack2(s[mi][2 * kk][2],     s[mi][2 * kk][3]);
                pa[mi][2] = pack2(s[mi][2 * kk + 1][0], s[mi][2 * kk + 1][1]);
                pa[mi][3] = pack2(s[mi][2 * kk + 1][2], s[mi][2 * kk + 1][3]);
            }
#pragma unroll
            for (int p = 0; p < 4; p++) {     // d 16-blocks
                uint32_t b0, b1, b2, b3;
                ldm_x4(b0, b1, b2, b3, v_addr + p * (16 * GST * 2) + kk * 32);
#pragma unroll
                for (int mi = 0; mi < 2; mi++) {
                    mma_fp16(o[mi][2 * p],     pa[mi][0], pa[mi][1], pa[mi][2], pa[mi][3], b0, b1);
                    mma_fp16(o[mi][2 * p + 1], pa[mi][0], pa[mi][1], pa[mi][2], pa[mi][3], b2, b3);
                }
            }
        }

        stg = (stg == 2) ? 0 : stg + 1;
        nstg = (nstg == 2) ? 0 : nstg + 1;
    }

    // epilogue: normalize, store fp16 to g_oh [B*T][C]
#pragma unroll
    for (int mi = 0; mi < 2; mi++) {
        const float inv0 = 1.0f / lA[mi];
        const float inv1 = 1.0f / lB[mi];
        const size_t r0 = (size_t)(b * NT + t0 + qbase + mi * 16 + g) * NC + h * HD;
        const size_t r1 = r0 + (size_t)8 * NC;
#pragma unroll
        for (int ni = 0; ni < 8; ni++) {
            const int col = ni * 8 + 2 * tg;
            *(uint32_t*)(g_oh + r0 + col) = pack2(o[mi][ni][0] * inv0, o[mi][ni][1] * inv0);
            *(uint32_t*)(g_oh + r1 + col) = pack2(o[mi][ni][2] * inv1, o[mi][ni][3] * inv1);
        }
    }
}

// ---------------- launch ------------------------------------------------------
extern "C" void kernel_launch(void* const* d_in, const int* in_sizes, int n_in,
                              void* d_out, int out_size)
{
    const float* x      = (const float*)d_in[0];
    const float* w_qkv  = (const float*)d_in[1];
    const float* b_qkv  = (const float*)d_in[2];
    const float* w_proj = (const float*)d_in[3];
    const float* b_proj = (const float*)d_in[4];
    float* out = (float*)d_out;

    float *p_qkv;
    __half *p_oh, *p_xh, *p_w1t, *p_w2t;
    cudaGetSymbolAddress((void**)&p_qkv, g_qkv);
    cudaGetSymbolAddress((void**)&p_oh,  g_oh);
    cudaGetSymbolAddress((void**)&p_xh,  g_xh);
    cudaGetSymbolAddress((void**)&p_w1t, g_w1t);
    cudaGetSymbolAddress((void**)&p_w2t, g_w2t);

    const int gemm_smem  = 3 * GSTB;     // 110592 B
    const int flash_smem = 3 * FSTB;     // 55296 B
    cudaFuncSetAttribute(gemm_fp16, cudaFuncAttributeMaxDynamicSharedMemorySize,
                         gemm_smem);
    cudaFuncSetAttribute(flash_fp16, cudaFuncAttributeMaxDynamicSharedMemorySize,
                         flash_smem);

    // 0) prep: x -> fp16; weights -> transposed fp16 [N][K]
    round_half<<<(NM * NC) / 1024, 256>>>(x, p_xh);
    {
        dim3 grid(N3C / 32, NC / 32);
        transpose_round_h<<<grid, 256>>>(w_qkv, p_w1t, NC, N3C);
    }
    {
        dim3 grid(NC / 32, NC / 32);
        transpose_round_h<<<grid, 256>>>(w_proj, p_w2t, NC, NC);
    }

    // 1) qkv = x @ w_qkv + b_qkv  (fp32 out)
    {
        dim3 grid(N3C / 128, NM / 128);
        gemm_fp16<<<grid, 256, gemm_smem>>>(p_xh, p_w1t, b_qkv, p_qkv, NM, N3C, NC);
    }
    // 2) rope Q,K -> fp16 [B,H,T,D] (Q pre-scaled by 1/8)
    {
        const int total_pairs = NM * NH * (HD / 2);
        rope_split<<<total_pairs / 256, 256>>>();
    }
    // 3) V -> fp16 [B,H,D,T]
    {
        dim3 grid(NT / 64, NH, NB);
        transpose_v<<<grid, 256>>>();
    }
    // 4) flash attention -> g_oh fp16
    {
        dim3 grid(NT / 128, NH, NB);
        flash_fp16<<<grid, 128, flash_smem>>>();
    }
    // 5) out = g_oh @ w_proj + b_proj
    {
        dim3 grid(NC / 128, NM / 128);
        gemm_fp16<<<grid, 256, gemm_smem>>>(p_oh, p_w2t, b_proj, out, NM, NC, NC);
    }
}

// round 15
// speedup vs baseline: 1.1014x; 1.0322x over previous
#include <cuda_runtime.h>
#include <cuda_fp16.h>
#include <math.h>
#include <stdint.h>

// Problem constants (fixed shapes)
#define NB 4
#define NT 2048
#define NH 16
#define NC 1024
#define HD 64
#define NM (NB*NT)         // 8192
#define N3C (3*NC)         // 3072

// ---------------- scratch ----------------------------------------------------
__device__ __half g_q[(size_t)NB * NH * NT * HD];   // rope(Q)*0.125, fp16 [B,H,T,D]
__device__ __half g_k[(size_t)NB * NH * NT * HD];   // rope(K), fp16 [B,H,T,D]
__device__ __half g_v[(size_t)NB * NH * NT * HD];   // V fp16 [B,H,T,D]
__device__ __half g_oh[(size_t)NM * NC];            // attn out fp16
__device__ __half g_xh[(size_t)NM * NC];            // x fp16
__device__ __half g_w1t[(size_t)N3C * NC];          // w_qkv^T fp16 [3072][1024]
__device__ __half g_w2t[(size_t)NC * NC];           // w_proj^T fp16

// ---------------- helpers ----------------------------------------------------
__device__ __forceinline__ uint32_t pack2(float lo, float hi) {
    __half2 h = __floats2half2_rn(lo, hi);
    return *reinterpret_cast<uint32_t*>(&h);
}

__device__ __forceinline__ void mma_fp16(float c[4],
                                         uint32_t a0, uint32_t a1, uint32_t a2, uint32_t a3,
                                         uint32_t b0, uint32_t b1) {
    asm volatile(
        "mma.sync.aligned.m16n8k16.row.col.f32.f16.f16.f32 "
        "{%0,%1,%2,%3}, {%4,%5,%6,%7}, {%8,%9}, {%0,%1,%2,%3};\n"
        : "+f"(c[0]), "+f"(c[1]), "+f"(c[2]), "+f"(c[3])
        : "r"(a0), "r"(a1), "r"(a2), "r"(a3), "r"(b0), "r"(b1));
}

__device__ __forceinline__ void ldm_x4(uint32_t& r0, uint32_t& r1,
                                       uint32_t& r2, uint32_t& r3, uint32_t addr) {
    asm volatile("ldmatrix.sync.aligned.m8n8.x4.shared.b16 {%0,%1,%2,%3}, [%4];"
                 : "=r"(r0), "=r"(r1), "=r"(r2), "=r"(r3) : "r"(addr));
}

__device__ __forceinline__ void ldm_x4_trans(uint32_t& r0, uint32_t& r1,
                                             uint32_t& r2, uint32_t& r3, uint32_t addr) {
    asm volatile("ldmatrix.sync.aligned.m8n8.x4.trans.shared.b16 {%0,%1,%2,%3}, [%4];"
                 : "=r"(r0), "=r"(r1), "=r"(r2), "=r"(r3) : "r"(addr));
}

__device__ __forceinline__ void cp16(uint32_t smem_addr, const void* gptr) {
    asm volatile("cp.async.cg.shared.global [%0], [%1], 16;\n"
                 :: "r"(smem_addr), "l"(gptr));
}
__device__ __forceinline__ void cp_commit() {
    asm volatile("cp.async.commit_group;\n");
}
template <int N>
__device__ __forceinline__ void cp_wait() {
    asm volatile("cp.async.wait_group %0;\n" :: "n"(N));
}
__device__ __forceinline__ uint32_t smem_u32(const void* p) {
    return (uint32_t)__cvta_generic_to_shared(p);
}

// ---------------- prep kernels -----------------------------------------------
__global__ __launch_bounds__(256) void round_half(const float* __restrict__ in,
                                                  __half* __restrict__ out) {
    const size_t i = ((size_t)blockIdx.x * 256 + threadIdx.x) * 4;
    float4 v = *(const float4*)(in + i);
    uint2 o;
    o.x = pack2(v.x, v.y);
    o.y = pack2(v.z, v.w);
    *(uint2*)(out + i) = o;
}

// transpose + round: in fp32 [R][Cc] -> out fp16 [Cc][R]
__global__ __launch_bounds__(256) void transpose_round_h(const float* __restrict__ in,
                                                         __half* __restrict__ out,
                                                         int R, int Cc) {
    __shared__ float t[32][33];
    const int c0 = blockIdx.x * 32, r0 = blockIdx.y * 32;
    const int tx = threadIdx.x & 31, ty = threadIdx.x >> 5;
#pragma unroll
    for (int i = 0; i < 32; i += 8)
        t[ty + i][tx] = in[(size_t)(r0 + ty + i) * Cc + c0 + tx];
    __syncthreads();
#pragma unroll
    for (int i = 0; i < 32; i += 8)
        out[(size_t)(c0 + ty + i) * R + r0 + tx] = __float2half_rn(t[tx][ty + i]);
}

// ---------------- shared GEMM mainloop config --------------------------------
#define GST 72                      // halfs per smem row (36 words)
#define GOPB (128 * GST * 2)        // bytes per operand per stage = 18432
#define GSTB (2 * GOPB)             // stage bytes = 36864

// ---------------- fused QKV GEMM + bias + RoPE + split ------------------------
// qkv = x @ w_qkv^T + b; Q/K rope'd (Q*0.125), all stored fp16 [B,H,T,D].
// grid (24, 64): bx = N-tile (third = bx>>3), by = M-tile. 256 thr.
__global__ __launch_bounds__(256) void gemm_qkv_fused(
    const __half* __restrict__ A, const __half* __restrict__ Bt,
    const float* __restrict__ bias)
{
    extern __shared__ uint32_t gsm[];

    const int bx = blockIdx.x, by = blockIdx.y;
    const int tid = threadIdx.x;
    const int lane = tid & 31, wid = tid >> 5;
    const int wm = (wid & 3) * 32;
    const int wn = (wid >> 2) * 64;
    const int K = NC;

    const uint32_t smem_base = smem_u32(gsm);

    const int lr = lane & 7, ts = lane >> 3;
    const uint32_t a_off = ((wm + (ts & 1) * 8 + lr) * GST + (ts >> 1) * 8) * 2;
    const uint32_t b_off = ((wn + (ts >> 1) * 8 + lr) * GST + (ts & 1) * 8) * 2;

    const __half* Ab  = A  + (size_t)(by * 128) * K;
    const __half* Btb = Bt + (size_t)(bx * 128) * K;

    auto load_stage = [&](int k0, int st) {
        const uint32_t base = smem_base + (uint32_t)st * GSTB;
#pragma unroll
        for (int t = 0; t < 4; t++) {
            const int ci = tid + t * 256;
            const int row = ci >> 3, cw = (ci & 7) * 8;
            cp16(base + (row * GST + cw) * 2,
                 Ab + (size_t)row * K + k0 + cw);
            cp16(base + GOPB + (row * GST + cw) * 2,
                 Btb + (size_t)row * K + k0 + cw);
        }
    };

    float c[2][8][4];
#pragma unroll
    for (int mi = 0; mi < 2; mi++)
#pragma unroll
        for (int ni = 0; ni < 8; ni++)
#pragma unroll
            for (int j = 0; j < 4; j++) c[mi][ni][j] = 0.f;

    const int nsteps = K / 64;
    load_stage(0, 0);
    cp_commit();
    load_stage(64, 1);
    cp_commit();

    int stg = 0, nstg = 2;
    for (int s = 0; s < nsteps; s++) {
        if (s < nsteps - 1) cp_wait<1>(); else cp_wait<0>();
        __syncthreads();
        if (s + 2 < nsteps) load_stage((s + 2) * 64, nstg);
        cp_commit();

        const uint32_t sb = smem_base + (uint32_t)stg * GSTB;
        const uint32_t a_addr = sb + a_off;
        const uint32_t b_addr = sb + GOPB + b_off;

#pragma unroll
        for (int kk = 0; kk < 4; kk++) {
            uint32_t a[2][4];
#pragma unroll
            for (int mi = 0; mi < 2; mi++)
                ldm_x4(a[mi][0], a[mi][1], a[mi][2], a[mi][3],
                       a_addr + mi * (16 * GST * 2) + kk * 32);
#pragma unroll
            for (int p = 0; p < 4; p++) {
                uint32_t b0, b1, b2, b3;
                ldm_x4(b0, b1, b2, b3, b_addr + p * (16 * GST * 2) + kk * 32);
                mma_fp16(c[0][2 * p],     a[0][0], a[0][1], a[0][2], a[0][3], b0, b1);
                mma_fp16(c[0][2 * p + 1], a[0][0], a[0][1], a[0][2], a[0][3], b2, b3);
                mma_fp16(c[1][2 * p],     a[1][0], a[1][1], a[1][2], a[1][3], b0, b1);
                mma_fp16(c[1][2 * p + 1], a[1][0], a[1][1], a[1][2], a[1][3], b2, b3);
            }
        }
        stg = (stg == 2) ? 0 : stg + 1;
        nstg = (nstg == 2) ? 0 : nstg + 1;
    }

    // ---- fused epilogue: bias + rope/split + fp16 store ----
    const int gg = lane >> 2, tt = lane & 3;
    const int third = bx >> 3;                 // 0:Q 1:K 2:V
    const int cbase = bx * 128 + wn;           // global col of warp

    float bz0[8], bz1[8], invf[8];
    int hh[8], dd[8];
#pragma unroll
    for (int ni = 0; ni < 8; ni++) {
        const int gc = cbase + ni * 8 + 2 * tt;
        bz0[ni] = bias[gc];
        bz1[ni] = bias[gc + 1];
        const int c1 = gc & 1023;              // within-third col
        hh[ni] = c1 >> 6;
        dd[ni] = c1 & 63;                      // even head-dim idx (pair base)
        invf[ni] = __expf(-(float)dd[ni] * (9.210340371976184f / 64.0f));
    }

#pragma unroll
    for (int mi = 0; mi < 2; mi++) {
#pragma unroll
        for (int r = 0; r < 2; r++) {
            const int m = by * 128 + wm + mi * 16 + gg + r * 8;
            const int bb = m >> 11, t = m & (NT - 1);
            const float tf = (float)t;
#pragma unroll
            for (int ni = 0; ni < 8; ni++) {
                float x0 = c[mi][ni][2 * r]     + bz0[ni];
                float x1 = c[mi][ni][2 * r + 1] + bz1[ni];
                const size_t oidx =
                    (((size_t)(bb * NH + hh[ni]) * NT + t) * HD) + dd[ni];
                if (third == 2) {
                    *(uint32_t*)(g_v + oidx) = pack2(x0, x1);
                } else {
                    float sn, cs;
                    sincosf(tf * invf[ni], &sn, &cs);
                    float r0 = x0 * cs - x1 * sn;
                    float r1 = x1 * cs + x0 * sn;
                    if (third == 0) {
                        *(uint32_t*)(g_q + oidx) = pack2(r0 * 0.125f, r1 * 0.125f);
                    } else {
                        *(uint32_t*)(g_k + oidx) = pack2(r0, r1);
                    }
                }
            }
        }
    }
}

// ---------------- plain fp16 GEMM (proj): CTA 128x128, warp 32x64 ------------
__global__ __launch_bounds__(256) void gemm_fp16(
    const __half* __restrict__ A, const __half* __restrict__ Bt,
    const float* __restrict__ bias, float* __restrict__ C,
    int M, int N, int K)
{
    extern __shared__ uint32_t gsm[];

    const int bx = blockIdx.x, by = blockIdx.y;
    const int tid = threadIdx.x;
    const int lane = tid & 31, wid = tid >> 5;
    const int wm = (wid & 3) * 32;
    const int wn = (wid >> 2) * 64;

    const uint32_t smem_base = smem_u32(gsm);

    const int lr = lane & 7, ts = lane >> 3;
    const uint32_t a_off = ((wm + (ts & 1) * 8 + lr) * GST + (ts >> 1) * 8) * 2;
    const uint32_t b_off = ((wn + (ts >> 1) * 8 + lr) * GST + (ts & 1) * 8) * 2;

    const __half* Ab  = A  + (size_t)(by * 128) * K;
    const __half* Btb = Bt + (size_t)(bx * 128) * K;

    auto load_stage = [&](int k0, int st) {
        const uint32_t base = smem_base + (uint32_t)st * GSTB;
#pragma unroll
        for (int t = 0; t < 4; t++) {
            const int ci = tid + t * 256;
            const int row = ci >> 3, cw = (ci & 7) * 8;
            cp16(base + (row * GST + cw) * 2,
                 Ab + (size_t)row * K + k0 + cw);
            cp16(base + GOPB + (row * GST + cw) * 2,
                 Btb + (size_t)row * K + k0 + cw);
        }
    };

    float c[2][8][4];
#pragma unroll
    for (int mi = 0; mi < 2; mi++)
#pragma unroll
        for (int ni = 0; ni < 8; ni++)
#pragma unroll
            for (int j = 0; j < 4; j++) c[mi][ni][j] = 0.f;

    const int nsteps = K / 64;
    load_stage(0, 0);
    cp_commit();
    load_stage(64, 1);
    cp_commit();

    int stg = 0, nstg = 2;
    for (int s = 0; s < nsteps; s++) {
        if (s < nsteps - 1) cp_wait<1>(); else cp_wait<0>();
        __syncthreads();
        if (s + 2 < nsteps) load_stage((s + 2) * 64, nstg);
        cp_commit();

        const uint32_t sb = smem_base + (uint32_t)stg * GSTB;
        const uint32_t a_addr = sb + a_off;
        const uint32_t b_addr = sb + GOPB + b_off;

#pragma unroll
        for (int kk = 0; kk < 4; kk++) {
            uint32_t a[2][4];
#pragma unroll
            for (int mi = 0; mi < 2; mi++)
                ldm_x4(a[mi][0], a[mi][1], a[mi][2], a[mi][3],
                       a_addr + mi * (16 * GST * 2) + kk * 32);
#pragma unroll
            for (int p = 0; p < 4; p++) {
                uint32_t b0, b1, b2, b3;
                ldm_x4(b0, b1, b2, b3, b_addr + p * (16 * GST * 2) + kk * 32);
                mma_fp16(c[0][2 * p],     a[0][0], a[0][1], a[0][2], a[0][3], b0, b1);
                mma_fp16(c[0][2 * p + 1], a[0][0], a[0][1], a[0][2], a[0][3], b2, b3);
                mma_fp16(c[1][2 * p],     a[1][0], a[1][1], a[1][2], a[1][3], b0, b1);
                mma_fp16(c[1][2 * p + 1], a[1][0], a[1][1], a[1][2], a[1][3], b2, b3);
            }
        }
        stg = (stg == 2) ? 0 : stg + 1;
        nstg = (nstg == 2) ? 0 : nstg + 1;
    }

    // epilogue: bias + fp32 store
    const int gg = lane >> 2, tt = lane & 3;
#pragma unroll
    for (int mi = 0; mi < 2; mi++) {
        const int r0 = by * 128 + wm + mi * 16 + gg;
#pragma unroll
        for (int ni = 0; ni < 8; ni++) {
            const int col = bx * 128 + wn + ni * 8 + 2 * tt;
            const float bz0 = bias[col], bz1 = bias[col + 1];
            *(float2*)(C + (size_t)r0 * N + col) =
                make_float2(c[mi][ni][0] + bz0, c[mi][ni][1] + bz1);
            *(float2*)(C + (size_t)(r0 + 8) * N + col) =
                make_float2(c[mi][ni][2] + bz0, c[mi][ni][3] + bz1);
        }
    }
}

// ---------------- Flash attention: 128 thr, 4 warps (32 q rows each) ---------
// BQ=128, BKV=64. V stored [B,H,T,D]; PV B-frags via ldmatrix.trans.
#define KOPB (64 * GST * 2)        // 9216 bytes (one 64-row tile)
#define FSTB (2 * KOPB)            // stage bytes = 18432 (K tile + V tile)

__global__ __launch_bounds__(128) void flash_fp16(void)
{
    extern __shared__ uint32_t fsm[];

    const int qt = blockIdx.x, h = blockIdx.y, b = blockIdx.z;
    const int t0 = qt * 128;
    const int tid = threadIdx.x;
    const int lane = tid & 31, wid = tid >> 5;
    const int g = lane >> 2, tg = lane & 3;
    const int qbase = wid * 32;          // 4 warps x 32 q rows

    const __half* Qb = g_q + (size_t)(b * NH + h) * NT * HD;
    const __half* Kb = g_k + (size_t)(b * NH + h) * NT * HD;
    const __half* Vb = g_v + (size_t)(b * NH + h) * NT * HD;

    const uint32_t smem_base = smem_u32(fsm);

    const int lr = lane & 7, ts = lane >> 3;
    // A-style (Q): (mlo,klo)(mhi,klo)(mlo,khi)(mhi,khi)
    const uint32_t qa_off = ((qbase + (ts & 1) * 8 + lr) * GST + (ts >> 1) * 8) * 2;
    // B-style (K rows=kv): (nlo,klo)(nlo,khi)(nhi,klo)(nhi,khi)
    const uint32_t fb_off = (((ts >> 1) * 8 + lr) * GST + (ts & 1) * 8) * 2;
    // trans B (V rows=kv, cols=d): (kvlo,dlo)(kvhi,dlo)(kvlo,dhi)(kvhi,dhi)
    const uint32_t vt_off = (((ts & 1) * 8 + lr) * GST + (ts >> 1) * 8) * 2;

    // stage Q tile [128][64 halfs] into stage 0
#pragma unroll
    for (int t = 0; t < 8; t++) {
        const int ci = tid + t * 128;        // 0..1023
        const int row = ci >> 3, cw = (ci & 7) * 8;
        cp16(smem_base + (row * GST + cw) * 2,
             Qb + (size_t)(t0 + row) * HD + cw);
    }
    cp_commit();
    cp_wait<0>();
    __syncthreads();

    uint32_t qa[4][2][4];                    // [kk][mi][frag]
#pragma unroll
    for (int kk = 0; kk < 4; kk++)
#pragma unroll
        for (int mi = 0; mi < 2; mi++)
            ldm_x4(qa[kk][mi][0], qa[kk][mi][1], qa[kk][mi][2], qa[kk][mi][3],
                   smem_base + qa_off + mi * (16 * GST * 2) + kk * 32);
    __syncthreads();   // qa reads done before stage-0 overwrite

    auto load_tile = [&](int kt, int buf) {
        const uint32_t base = smem_base + (uint32_t)buf * FSTB;
#pragma unroll
        for (int t = 0; t < 4; t++) {
            const int ci = tid + t * 128;    // 0..511
            const int row = ci >> 3, cw = (ci & 7) * 8;
            cp16(base + (row * GST + cw) * 2,
                 Kb + (size_t)(kt * 64 + row) * HD + cw);
            cp16(base + KOPB + (row * GST + cw) * 2,
                 Vb + (size_t)(kt * 64 + row) * HD + cw);
        }
    };

    float o[2][8][4];
#pragma unroll
    for (int mi = 0; mi < 2; mi++)
#pragma unroll
        for (int ni = 0; ni < 8; ni++)
#pragma unroll
            for (int j = 0; j < 4; j++) o[mi][ni][j] = 0.f;
    float mA[2] = {-INFINITY, -INFINITY}, mB[2] = {-INFINITY, -INFINITY};
    float lA[2] = {0.f, 0.f}, lB[2] = {0.f, 0.f};

    load_tile(0, 0);
    cp_commit();
    load_tile(1, 1);
    cp_commit();

    const int NITER = NT / 64;
    int stg = 0, nstg = 2;
    for (int kt = 0; kt < NITER; kt++) {
        if (kt < NITER - 1) cp_wait<1>(); else cp_wait<0>();
        __syncthreads();
        if (kt + 2 < NITER) load_tile(kt + 2, nstg);
        cp_commit();

        const uint32_t k_addr = smem_base + (uint32_t)stg * FSTB + fb_off;
        const uint32_t v_addr = smem_base + (uint32_t)stg * FSTB + KOPB + vt_off;

        // S = (Q*0.125) @ K^T   (warp: 32 q x 64 kv)
        float s[2][8][4];
#pragma unroll
        for (int mi = 0; mi < 2; mi++)
#pragma unroll
            for (int ni = 0; ni < 8; ni++)
#pragma unroll
                for (int j = 0; j < 4; j++) s[mi][ni][j] = 0.f;

#pragma unroll
        for (int kk = 0; kk < 4; kk++) {
#pragma unroll
            for (int p = 0; p < 4; p++) {
                uint32_t b0, b1, b2, b3;
                ldm_x4(b0, b1, b2, b3, k_addr + p * (16 * GST * 2) + kk * 32);
#pragma unroll
                for (int mi = 0; mi < 2; mi++) {
                    mma_fp16(s[mi][2 * p],     qa[kk][mi][0], qa[kk][mi][1],
                             qa[kk][mi][2], qa[kk][mi][3], b0, b1);
                    mma_fp16(s[mi][2 * p + 1], qa[kk][mi][0], qa[kk][mi][1],
                             qa[kk][mi][2], qa[kk][mi][3], b2, b3);
                }
            }
        }

        // online softmax per mi (rows qbase+mi*16+g and +8)
#pragma unroll
        for (int mi = 0; mi < 2; mi++) {
            float mx0 = -INFINITY, mx1 = -INFINITY;
#pragma unroll
            for (int ni = 0; ni < 8; ni++) {
                mx0 = fmaxf(mx0, fmaxf(s[mi][ni][0], s[mi][ni][1]));
                mx1 = fmaxf(mx1, fmaxf(s[mi][ni][2], s[mi][ni][3]));
            }
            mx0 = fmaxf(mx0, __shfl_xor_sync(0xffffffffu, mx0, 1));
            mx0 = fmaxf(mx0, __shfl_xor_sync(0xffffffffu, mx0, 2));
            mx1 = fmaxf(mx1, __shfl_xor_sync(0xffffffffu, mx1, 1));
            mx1 = fmaxf(mx1, __shfl_xor_sync(0xffffffffu, mx1, 2));

            const float mn0 = fmaxf(mA[mi], mx0);
            const float mn1 = fmaxf(mB[mi], mx1);
            const float al0 = __expf(mA[mi] - mn0);
            const float al1 = __expf(mB[mi] - mn1);
            mA[mi] = mn0; mB[mi] = mn1;

            float sum0 = 0.f, sum1 = 0.f;
#pragma unroll
            for (int ni = 0; ni < 8; ni++) {
                s[mi][ni][0] = __expf(s[mi][ni][0] - mn0);
                s[mi][ni][1] = __expf(s[mi][ni][1] - mn0);
                s[mi][ni][2] = __expf(s[mi][ni][2] - mn1);
                s[mi][ni][3] = __expf(s[mi][ni][3] - mn1);
                sum0 += s[mi][ni][0] + s[mi][ni][1];
                sum1 += s[mi][ni][2] + s[mi][ni][3];
                o[mi][ni][0] *= al0; o[mi][ni][1] *= al0;
                o[mi][ni][2] *= al1; o[mi][ni][3] *= al1;
            }
            sum0 += __shfl_xor_sync(0xffffffffu, sum0, 1);
            sum0 += __shfl_xor_sync(0xffffffffu, sum0, 2);
            sum1 += __shfl_xor_sync(0xffffffffu, sum1, 1);
            sum1 += __shfl_xor_sync(0xffffffffu, sum1, 2);
            lA[mi] = lA[mi] * al0 + sum0;
            lB[mi] = lB[mi] * al1 + sum1;
        }

        // O += P @ V : V B-frags via ldmatrix.trans from [kv][d] tile
#pragma unroll
        for (int kk = 0; kk < 4; kk++) {      // kv 16-chunks
            uint32_t pa[2][4];
#pragma unroll
            for (int mi = 0; mi < 2; mi++) {
                pa[mi][0] = pack2(s[mi][2 * kk][0],     s[mi][2 * kk][1]);
                pa[mi][1] = pack2(s[mi][2 * kk][2],     s[mi][2 * kk][3]);
                pa[mi][2] = pack2(s[mi][2 * kk + 1][0], s[mi][2 * kk + 1][1]);
                pa[mi][3] = pack2(s[mi][2 * kk + 1][2], s[mi][2 * kk + 1][3]);
            }
#pragma unroll
            for (int p = 0; p < 4; p++) {     // d 16-blocks
                uint32_t b0, b1, b2, b3;
                ldm_x4_trans(b0, b1, b2, b3,
                             v_addr + kk * (16 * GST * 2) + p * 32);
#pragma unroll
                for (int mi = 0; mi < 2; mi++) {
                    mma_fp16(o[mi][2 * p],     pa[mi][0], pa[mi][1], pa[mi][2], pa[mi][3], b0, b1);
                    mma_fp16(o[mi][2 * p + 1], pa[mi][0], pa[mi][1], pa[mi][2], pa[mi][3], b2, b3);
                }
            }
        }

        stg = (stg == 2) ? 0 : stg + 1;
        nstg = (nstg == 2) ? 0 : nstg + 1;
    }

    // epilogue: normalize, store fp16 to g_oh [B*T][C]
#pragma unroll
    for (int mi = 0; mi < 2; mi++) {
        const float inv0 = 1.0f / lA[mi];
        const float inv1 = 1.0f / lB[mi];
        const size_t r0 = (size_t)(b * NT + t0 + qbase + mi * 16 + g) * NC + h * HD;
        const size_t r1 = r0 + (size_t)8 * NC;
#pragma unroll
        for (int ni = 0; ni < 8; ni++) {
            const int col = ni * 8 + 2 * tg;
            *(uint32_t*)(g_oh + r0 + col) = pack2(o[mi][ni][0] * inv0, o[mi][ni][1] * inv0);
            *(uint32_t*)(g_oh + r1 + col) = pack2(o[mi][ni][2] * inv1, o[mi][ni][3] * inv1);
        }
    }
}

// ---------------- launch ------------------------------------------------------
extern "C" void kernel_launch(void* const* d_in, const int* in_sizes, int n_in,
                              void* d_out, int out_size)
{
    const float* x      = (const float*)d_in[0];
    const float* w_qkv  = (const float*)d_in[1];
    const float* b_qkv  = (const float*)d_in[2];
    const float* w_proj = (const float*)d_in[3];
    const float* b_proj = (const float*)d_in[4];
    float* out = (float*)d_out;

    __half *p_oh, *p_xh, *p_w1t, *p_w2t;
    cudaGetSymbolAddress((void**)&p_oh,  g_oh);
    cudaGetSymbolAddress((void**)&p_xh,  g_xh);
    cudaGetSymbolAddress((void**)&p_w1t, g_w1t);
    cudaGetSymbolAddress((void**)&p_w2t, g_w2t);

    const int gemm_smem  = 3 * GSTB;     // 110592 B
    const int flash_smem = 3 * FSTB;     // 55296 B
    cudaFuncSetAttribute(gemm_qkv_fused, cudaFuncAttributeMaxDynamicSharedMemorySize,
                         gemm_smem);
    cudaFuncSetAttribute(gemm_fp16, cudaFuncAttributeMaxDynamicSharedMemorySize,
                         gemm_smem);
    cudaFuncSetAttribute(flash_fp16, cudaFuncAttributeMaxDynamicSharedMemorySize,
                         flash_smem);

    // 0) prep: x -> fp16; weights -> transposed fp16 [N][K]
    round_half<<<(NM * NC) / 1024, 256>>>(x, p_xh);
    {
        dim3 grid(N3C / 32, NC / 32);
        transpose_round_h<<<grid, 256>>>(w_qkv, p_w1t, NC, N3C);
    }
    {
        dim3 grid(NC / 32, NC / 32);
        transpose_round_h<<<grid, 256>>>(w_proj, p_w2t, NC, NC);
    }

    // 1) fused qkv GEMM + bias + rope + split -> g_q/g_k/g_v fp16 [B,H,T,D]
    {
        dim3 grid(N3C / 128, NM / 128);
        gemm_qkv_fused<<<grid, 256, gemm_smem>>>(p_xh, p_w1t, b_qkv);
    }
    // 2) flash attention -> g_oh fp16
    {
        dim3 grid(NT / 128, NH, NB);
        flash_fp16<<<grid, 128, flash_smem>>>();
    }
    // 3) out = g_oh @ w_proj + b_proj
    {
        dim3 grid(NC / 128, NM / 128);
        gemm_fp16<<<grid, 256, gemm_smem>>>(p_oh, p_w2t, b_proj, out, NM, NC, NC);
    }
}

// round 17
// speedup vs baseline: 1.1114x; 1.0091x over previous
#include <cuda_runtime.h>
#include <cuda_fp16.h>
#include <math.h>
#include <stdint.h>

// Problem constants (fixed shapes)
#define NB 4
#define NT 2048
#define NH 16
#define NC 1024
#define HD 64
#define NM (NB*NT)         // 8192
#define N3C (3*NC)         // 3072

#define LOG2E 1.4426950408889634f

// ---------------- scratch ----------------------------------------------------
__device__ __half g_q[(size_t)NB * NH * NT * HD];   // rope(Q)*0.125*log2e, fp16 [B,H,T,D]
__device__ __half g_k[(size_t)NB * NH * NT * HD];   // rope(K), fp16 [B,H,T,D]
__device__ __half g_v[(size_t)NB * NH * NT * HD];   // V fp16 [B,H,T,D]
__device__ __half g_oh[(size_t)NM * NC];            // attn out fp16
__device__ __half g_xh[(size_t)NM * NC];            // x fp16
__device__ __half g_w1t[(size_t)N3C * NC];          // w_qkv^T fp16 [3072][1024]
__device__ __half g_w2t[(size_t)NC * NC];           // w_proj^T fp16
__device__ float  g_rope[(size_t)NT * HD];          // [t][2i]=cos, [t][2i+1]=sin

// ---------------- helpers ----------------------------------------------------
__device__ __forceinline__ uint32_t pack2(float lo, float hi) {
    __half2 h = __floats2half2_rn(lo, hi);
    return *reinterpret_cast<uint32_t*>(&h);
}

__device__ __forceinline__ void mma_fp16(float c[4],
                                         uint32_t a0, uint32_t a1, uint32_t a2, uint32_t a3,
                                         uint32_t b0, uint32_t b1) {
    asm volatile(
        "mma.sync.aligned.m16n8k16.row.col.f32.f16.f16.f32 "
        "{%0,%1,%2,%3}, {%4,%5,%6,%7}, {%8,%9}, {%0,%1,%2,%3};\n"
        : "+f"(c[0]), "+f"(c[1]), "+f"(c[2]), "+f"(c[3])
        : "r"(a0), "r"(a1), "r"(a2), "r"(a3), "r"(b0), "r"(b1));
}

__device__ __forceinline__ void ldm_x4(uint32_t& r0, uint32_t& r1,
                                       uint32_t& r2, uint32_t& r3, uint32_t addr) {
    asm volatile("ldmatrix.sync.aligned.m8n8.x4.shared.b16 {%0,%1,%2,%3}, [%4];"
                 : "=r"(r0), "=r"(r1), "=r"(r2), "=r"(r3) : "r"(addr));
}

__device__ __forceinline__ void ldm_x4_trans(uint32_t& r0, uint32_t& r1,
                                             uint32_t& r2, uint32_t& r3, uint32_t addr) {
    asm volatile("ldmatrix.sync.aligned.m8n8.x4.trans.shared.b16 {%0,%1,%2,%3}, [%4];"
                 : "=r"(r0), "=r"(r1), "=r"(r2), "=r"(r3) : "r"(addr));
}

__device__ __forceinline__ void cp16(uint32_t smem_addr, const void* gptr) {
    asm volatile("cp.async.cg.shared.global [%0], [%1], 16;\n"
                 :: "r"(smem_addr), "l"(gptr));
}
__device__ __forceinline__ void cp_commit() {
    asm volatile("cp.async.commit_group;\n");
}
template <int N>
__device__ __forceinline__ void cp_wait() {
    asm volatile("cp.async.wait_group %0;\n" :: "n"(N));
}
__device__ __forceinline__ uint32_t smem_u32(const void* p) {
    return (uint32_t)__cvta_generic_to_shared(p);
}

// ---------------- prep kernels -----------------------------------------------
__global__ __launch_bounds__(256) void rope_table(void)
{
    const int idx = blockIdx.x * 256 + threadIdx.x;   // 0..65535
    const int t = idx >> 5, i = idx & 31;
    const float inv_freq = __expf(-(float)(2 * i) * (9.210340371976184f / 64.0f));
    float sn, cs;
    sincosf((float)t * inv_freq, &sn, &cs);
    g_rope[t * HD + 2 * i]     = cs;
    g_rope[t * HD + 2 * i + 1] = sn;
}

__global__ __launch_bounds__(256) void round_half(const float* __restrict__ in,
                                                  __half* __restrict__ out) {
    const size_t i = ((size_t)blockIdx.x * 256 + threadIdx.x) * 4;
    float4 v = *(const float4*)(in + i);
    uint2 o;
    o.x = pack2(v.x, v.y);
    o.y = pack2(v.z, v.w);
    *(uint2*)(out + i) = o;
}

// transpose + round: in fp32 [R][Cc] -> out fp16 [Cc][R]
__global__ __launch_bounds__(256) void transpose_round_h(const float* __restrict__ in,
                                                         __half* __restrict__ out,
                                                         int R, int Cc) {
    __shared__ float t[32][33];
    const int c0 = blockIdx.x * 32, r0 = blockIdx.y * 32;
    const int tx = threadIdx.x & 31, ty = threadIdx.x >> 5;
#pragma unroll
    for (int i = 0; i < 32; i += 8)
        t[ty + i][tx] = in[(size_t)(r0 + ty + i) * Cc + c0 + tx];
    __syncthreads();
#pragma unroll
    for (int i = 0; i < 32; i += 8)
        out[(size_t)(c0 + ty + i) * R + r0 + tx] = __float2half_rn(t[tx][ty + i]);
}

// ---------------- shared GEMM mainloop config --------------------------------
#define GST 72                      // halfs per smem row (36 words)
#define GOPB (128 * GST * 2)        // bytes per operand per stage = 18432
#define GSTB (2 * GOPB)             // stage bytes = 36864

// ---------------- fused QKV GEMM + bias + RoPE + split ------------------------
// qkv = x @ w_qkv^T + b; Q/K rope'd (Q*0.125*log2e), stored fp16 [B,H,T,D].
// grid (24, 64): bx = N-tile (third = bx>>3), by = M-tile. 256 thr.
__global__ __launch_bounds__(256) void gemm_qkv_fused(
    const __half* __restrict__ A, const __half* __restrict__ Bt,
    const float* __restrict__ bias)
{
    extern __shared__ uint32_t gsm[];

    const int bx = blockIdx.x, by = blockIdx.y;
    const int tid = threadIdx.x;
    const int lane = tid & 31, wid = tid >> 5;
    const int wm = (wid & 3) * 32;
    const int wn = (wid >> 2) * 64;
    const int K = NC;

    const uint32_t smem_base = smem_u32(gsm);

    const int lr = lane & 7, ts = lane >> 3;
    const uint32_t a_off = ((wm + (ts & 1) * 8 + lr) * GST + (ts >> 1) * 8) * 2;
    const uint32_t b_off = ((wn + (ts >> 1) * 8 + lr) * GST + (ts & 1) * 8) * 2;

    const __half* Ab  = A  + (size_t)(by * 128) * K;
    const __half* Btb = Bt + (size_t)(bx * 128) * K;

    auto load_stage = [&](int k0, int st) {
        const uint32_t base = smem_base + (uint32_t)st * GSTB;
#pragma unroll
        for (int t = 0; t < 4; t++) {
            const int ci = tid + t * 256;
            const int row = ci >> 3, cw = (ci & 7) * 8;
            cp16(base + (row * GST + cw) * 2,
                 Ab + (size_t)row * K + k0 + cw);
            cp16(base + GOPB + (row * GST + cw) * 2,
                 Btb + (size_t)row * K + k0 + cw);
        }
    };

    float c[2][8][4];
#pragma unroll
    for (int mi = 0; mi < 2; mi++)
#pragma unroll
        for (int ni = 0; ni < 8; ni++)
#pragma unroll
            for (int j = 0; j < 4; j++) c[mi][ni][j] = 0.f;

    const int nsteps = K / 64;
    load_stage(0, 0);
    cp_commit();
    load_stage(64, 1);
    cp_commit();

    int stg = 0, nstg = 2;
    for (int s = 0; s < nsteps; s++) {
        if (s < nsteps - 1) cp_wait<1>(); else cp_wait<0>();
        __syncthreads();
        if (s + 2 < nsteps) load_stage((s + 2) * 64, nstg);
        cp_commit();

        const uint32_t sb = smem_base + (uint32_t)stg * GSTB;
        const uint32_t a_addr = sb + a_off;
        const uint32_t b_addr = sb + GOPB + b_off;

#pragma unroll
        for (int kk = 0; kk < 4; kk++) {
            uint32_t a[2][4];
#pragma unroll
            for (int mi = 0; mi < 2; mi++)
                ldm_x4(a[mi][0], a[mi][1], a[mi][2], a[mi][3],
                       a_addr + mi * (16 * GST * 2) + kk * 32);
#pragma unroll
            for (int p = 0; p < 4; p++) {
                uint32_t b0, b1, b2, b3;
                ldm_x4(b0, b1, b2, b3, b_addr + p * (16 * GST * 2) + kk * 32);
                mma_fp16(c[0][2 * p],     a[0][0], a[0][1], a[0][2], a[0][3], b0, b1);
                mma_fp16(c[0][2 * p + 1], a[0][0], a[0][1], a[0][2], a[0][3], b2, b3);
                mma_fp16(c[1][2 * p],     a[1][0], a[1][1], a[1][2], a[1][3], b0, b1);
                mma_fp16(c[1][2 * p + 1], a[1][0], a[1][1], a[1][2], a[1][3], b2, b3);
            }
        }
        stg = (stg == 2) ? 0 : stg + 1;
        nstg = (nstg == 2) ? 0 : nstg + 1;
    }

    // ---- fused epilogue: bias + rope (table) + split + fp16 store ----
    const int gg = lane >> 2, tt = lane & 3;
    const int third = bx >> 3;                 // 0:Q 1:K 2:V
    const int cbase = bx * 128 + wn;           // global col of warp

    float bz0[8], bz1[8];
    int hh[8], dd[8];
#pragma unroll
    for (int ni = 0; ni < 8; ni++) {
        const int gc = cbase + ni * 8 + 2 * tt;
        bz0[ni] = bias[gc];
        bz1[ni] = bias[gc + 1];
        const int c1 = gc & 1023;              // within-third col
        hh[ni] = c1 >> 6;
        dd[ni] = c1 & 63;                      // even head-dim idx (pair base)
    }

#pragma unroll
    for (int mi = 0; mi < 2; mi++) {
#pragma unroll
        for (int r = 0; r < 2; r++) {
            const int m = by * 128 + wm + mi * 16 + gg + r * 8;
            const int bb = m >> 11, t = m & (NT - 1);
            const float* rt = g_rope + t * HD;
#pragma unroll
            for (int ni = 0; ni < 8; ni++) {
                float x0 = c[mi][ni][2 * r]     + bz0[ni];
                float x1 = c[mi][ni][2 * r + 1] + bz1[ni];
                const size_t oidx =
                    (((size_t)(bb * NH + hh[ni]) * NT + t) * HD) + dd[ni];
                if (third == 2) {
                    *(uint32_t*)(g_v + oidx) = pack2(x0, x1);
                } else {
                    const float2 cssn = *(const float2*)(rt + dd[ni]);
                    float r0 = x0 * cssn.x - x1 * cssn.y;
                    float r1 = x1 * cssn.x + x0 * cssn.y;
                    if (third == 0) {
                        *(uint32_t*)(g_q + oidx) =
                            pack2(r0 * (0.125f * LOG2E), r1 * (0.125f * LOG2E));
                    } else {
                        *(uint32_t*)(g_k + oidx) = pack2(r0, r1);
                    }
                }
            }
        }
    }
}

// ---------------- plain fp16 GEMM (proj): CTA 128x128, warp 32x64 ------------
__global__ __launch_bounds__(256) void gemm_fp16(
    const __half* __restrict__ A, const __half* __restrict__ Bt,
    const float* __restrict__ bias, float* __restrict__ C,
    int M, int N, int K)
{
    extern __shared__ uint32_t gsm[];

    const int bx = blockIdx.x, by = blockIdx.y;
    const int tid = threadIdx.x;
    const int lane = tid & 31, wid = tid >> 5;
    const int wm = (wid & 3) * 32;
    const int wn = (wid >> 2) * 64;

    const uint32_t smem_base = smem_u32(gsm);

    const int lr = lane & 7, ts = lane >> 3;
    const uint32_t a_off = ((wm + (ts & 1) * 8 + lr) * GST + (ts >> 1) * 8) * 2;
    const uint32_t b_off = ((wn + (ts >> 1) * 8 + lr) * GST + (ts & 1) * 8) * 2;

    const __half* Ab  = A  + (size_t)(by * 128) * K;
    const __half* Btb = Bt + (size_t)(bx * 128) * K;

    auto load_stage = [&](int k0, int st) {
        const uint32_t base = smem_base + (uint32_t)st * GSTB;
#pragma unroll
        for (int t = 0; t < 4; t++) {
            const int ci = tid + t * 256;
            const int row = ci >> 3, cw = (ci & 7) * 8;
            cp16(base + (row * GST + cw) * 2,
                 Ab + (size_t)row * K + k0 + cw);
            cp16(base + GOPB + (row * GST + cw) * 2,
                 Btb + (size_t)row * K + k0 + cw);
        }
    };

    float c[2][8][4];
#pragma unroll
    for (int mi = 0; mi < 2; mi++)
#pragma unroll
        for (int ni = 0; ni < 8; ni++)
#pragma unroll
            for (int j = 0; j < 4; j++) c[mi][ni][j] = 0.f;

    const int nsteps = K / 64;
    load_stage(0, 0);
    cp_commit();
    load_stage(64, 1);
    cp_commit();

    int stg = 0, nstg = 2;
    for (int s = 0; s < nsteps; s++) {
        if (s < nsteps - 1) cp_wait<1>(); else cp_wait<0>();
        __syncthreads();
        if (s + 2 < nsteps) load_stage((s + 2) * 64, nstg);
        cp_commit();

        const uint32_t sb = smem_base + (uint32_t)stg * GSTB;
        const uint32_t a_addr = sb + a_off;
        const uint32_t b_addr = sb + GOPB + b_off;

#pragma unroll
        for (int kk = 0; kk < 4; kk++) {
            uint32_t a[2][4];
#pragma unroll
            for (int mi = 0; mi < 2; mi++)
                ldm_x4(a[mi][0], a[mi][1], a[mi][2], a[mi][3],
                       a_addr + mi * (16 * GST * 2) + kk * 32);
#pragma unroll
            for (int p = 0; p < 4; p++) {
                uint32_t b0, b1, b2, b3;
                ldm_x4(b0, b1, b2, b3, b_addr + p * (16 * GST * 2) + kk * 32);
                mma_fp16(c[0][2 * p],     a[0][0], a[0][1], a[0][2], a[0][3], b0, b1);
                mma_fp16(c[0][2 * p + 1], a[0][0], a[0][1], a[0][2], a[0][3], b2, b3);
                mma_fp16(c[1][2 * p],     a[1][0], a[1][1], a[1][2], a[1][3], b0, b1);
                mma_fp16(c[1][2 * p + 1], a[1][0], a[1][1], a[1][2], a[1][3], b2, b3);
            }
        }
        stg = (stg == 2) ? 0 : stg + 1;
        nstg = (nstg == 2) ? 0 : nstg + 1;
    }

    // epilogue: bias + fp32 store
    const int gg = lane >> 2, tt = lane & 3;
#pragma unroll
    for (int mi = 0; mi < 2; mi++) {
        const int r0 = by * 128 + wm + mi * 16 + gg;
#pragma unroll
        for (int ni = 0; ni < 8; ni++) {
            const int col = bx * 128 + wn + ni * 8 + 2 * tt;
            const float bz0 = bias[col], bz1 = bias[col + 1];
            *(float2*)(C + (size_t)r0 * N + col) =
                make_float2(c[mi][ni][0] + bz0, c[mi][ni][1] + bz1);
            *(float2*)(C + (size_t)(r0 + 8) * N + col) =
                make_float2(c[mi][ni][2] + bz0, c[mi][ni][3] + bz1);
        }
    }
}

// ---------------- Flash attention: 128 thr, 4 warps (32 q rows each) ---------
// BQ=128, BKV=64. V stored [B,H,T,D]; PV B-frags via ldmatrix.trans.
// Softmax in exp2 domain (log2e folded into Q scale).
#define KOPB (64 * GST * 2)        // 9216 bytes (one 64-row tile)
#define FSTB (2 * KOPB)            // stage bytes = 18432 (K tile + V tile)

__global__ __launch_bounds__(128) void flash_fp16(void)
{
    extern __shared__ uint32_t fsm[];

    const int qt = blockIdx.x, h = blockIdx.y, b = blockIdx.z;
    const int t0 = qt * 128;
    const int tid = threadIdx.x;
    const int lane = tid & 31, wid = tid >> 5;
    const int g = lane >> 2, tg = lane & 3;
    const int qbase = wid * 32;          // 4 warps x 32 q rows

    const __half* Qb = g_q + (size_t)(b * NH + h) * NT * HD;
    const __half* Kb = g_k + (size_t)(b * NH + h) * NT * HD;
    const __half* Vb = g_v + (size_t)(b * NH + h) * NT * HD;

    const uint32_t smem_base = smem_u32(fsm);

    const int lr = lane & 7, ts = lane >> 3;
    // A-style (Q): (mlo,klo)(mhi,klo)(mlo,khi)(mhi,khi)
    const uint32_t qa_off = ((qbase + (ts & 1) * 8 + lr) * GST + (ts >> 1) * 8) * 2;
    // B-style (K rows=kv): (nlo,klo)(nlo,khi)(nhi,klo)(nhi,khi)
    const uint32_t fb_off = (((ts >> 1) * 8 + lr) * GST + (ts & 1) * 8) * 2;
    // trans B (V rows=kv, cols=d): (kvlo,dlo)(kvhi,dlo)(kvlo,dhi)(kvhi,dhi)
    const uint32_t vt_off = (((ts & 1) * 8 + lr) * GST + (ts >> 1) * 8) * 2;

    // stage Q tile [128][64 halfs] into stage 0
#pragma unroll
    for (int t = 0; t < 8; t++) {
        const int ci = tid + t * 128;        // 0..1023
        const int row = ci >> 3, cw = (ci & 7) * 8;
        cp16(smem_base + (row * GST + cw) * 2,
             Qb + (size_t)(t0 + row) * HD + cw);
    }
    cp_commit();
    cp_wait<0>();
    __syncthreads();

    uint32_t qa[4][2][4];                    // [kk][mi][frag]
#pragma unroll
    for (int kk = 0; kk < 4; kk++)
#pragma unroll
        for (int mi = 0; mi < 2; mi++)
            ldm_x4(qa[kk][mi][0], qa[kk][mi][1], qa[kk][mi][2], qa[kk][mi][3],
                   smem_base + qa_off + mi * (16 * GST * 2) + kk * 32);
    __syncthreads();   // qa reads done before stage-0 overwrite

    auto load_tile = [&](int kt, int buf) {
        const uint32_t base = smem_base + (uint32_t)buf * FSTB;
#pragma unroll
        for (int t = 0; t < 4; t++) {
            const int ci = tid + t * 128;    // 0..511
            const int row = ci >> 3, cw = (ci & 7) * 8;
            cp16(base + (row * GST + cw) * 2,
                 Kb + (size_t)(kt * 64 + row) * HD + cw);
            cp16(base + KOPB + (row * GST + cw) * 2,
                 Vb + (size_t)(kt * 64 + row) * HD + cw);
        }
    };

    float o[2][8][4];
#pragma unroll
    for (int mi = 0; mi < 2; mi++)
#pragma unroll
        for (int ni = 0; ni < 8; ni++)
#pragma unroll
            for (int j = 0; j < 4; j++) o[mi][ni][j] = 0.f;
    float mA[2] = {-INFINITY, -INFINITY}, mB[2] = {-INFINITY, -INFINITY};
    float lA[2] = {0.f, 0.f}, lB[2] = {0.f, 0.f};

    load_tile(0, 0);
    cp_commit();
    load_tile(1, 1);
    cp_commit();

    const int NITER = NT / 64;
    int stg = 0, nstg = 2;
    for (int kt = 0; kt < NITER; kt++) {
        if (kt < NITER - 1) cp_wait<1>(); else cp_wait<0>();
        __syncthreads();
        if (kt + 2 < NITER) load_tile(kt + 2, nstg);
        cp_commit();

        const uint32_t k_addr = smem_base + (uint32_t)stg * FSTB + fb_off;
        const uint32_t v_addr = smem_base + (uint32_t)stg * FSTB + KOPB + vt_off;

        // S = (Q*0.125*log2e) @ K^T   (warp: 32 q x 64 kv), log2 domain
        float s[2][8][4];
#pragma unroll
        for (int mi = 0; mi < 2; mi++)
#pragma unroll
            for (int ni = 0; ni < 8; ni++)
#pragma unroll
                for (int j = 0; j < 4; j++) s[mi][ni][j] = 0.f;

#pragma unroll
        for (int kk = 0; kk < 4; kk++) {
#pragma unroll
            for (int p = 0; p < 4; p++) {
                uint32_t b0, b1, b2, b3;
                ldm_x4(b0, b1, b2, b3, k_addr + p * (16 * GST * 2) + kk * 32);
#pragma unroll
                for (int mi = 0; mi < 2; mi++) {
                    mma_fp16(s[mi][2 * p],     qa[kk][mi][0], qa[kk][mi][1],
                             qa[kk][mi][2], qa[kk][mi][3], b0, b1);
                    mma_fp16(s[mi][2 * p + 1], qa[kk][mi][0], qa[kk][mi][1],
                             qa[kk][mi][2], qa[kk][mi][3], b2, b3);
                }
            }
        }

        // online softmax per mi (rows qbase+mi*16+g and +8), exp2 domain
#pragma unroll
        for (int mi = 0; mi < 2; mi++) {
            float mx0 = -INFINITY, mx1 = -INFINITY;
#pragma unroll
            for (int ni = 0; ni < 8; ni++) {
                mx0 = fmaxf(mx0, fmaxf(s[mi][ni][0], s[mi][ni][1]));
                mx1 = fmaxf(mx1, fmaxf(s[mi][ni][2], s[mi][ni][3]));
            }
            mx0 = fmaxf(mx0, __shfl_xor_sync(0xffffffffu, mx0, 1));
            mx0 = fmaxf(mx0, __shfl_xor_sync(0xffffffffu, mx0, 2));
            mx1 = fmaxf(mx1, __shfl_xor_sync(0xffffffffu, mx1, 1));
            mx1 = fmaxf(mx1, __shfl_xor_sync(0xffffffffu, mx1, 2));

            const float mn0 = fmaxf(mA[mi], mx0);
            const float mn1 = fmaxf(mB[mi], mx1);
            const float al0 = exp2f(mA[mi] - mn0);
            const float al1 = exp2f(mB[mi] - mn1);
            mA[mi] = mn0; mB[mi] = mn1;

            float sum0 = 0.f, sum1 = 0.f;
#pragma unroll
            for (int ni = 0; ni < 8; ni++) {
                s[mi][ni][0] = exp2f(s[mi][ni][0] - mn0);
                s[mi][ni][1] = exp2f(s[mi][ni][1] - mn0);
                s[mi][ni][2] = exp2f(s[mi][ni][2] - mn1);
                s[mi][ni][3] = exp2f(s[mi][ni][3] - mn1);
                sum0 += s[mi][ni][0] + s[mi][ni][1];
                sum1 += s[mi][ni][2] + s[mi][ni][3];
                o[mi][ni][0] *= al0; o[mi][ni][1] *= al0;
                o[mi][ni][2] *= al1; o[mi][ni][3] *= al1;
            }
            sum0 += __shfl_xor_sync(0xffffffffu, sum0, 1);
            sum0 += __shfl_xor_sync(0xffffffffu, sum0, 2);
            sum1 += __shfl_xor_sync(0xffffffffu, sum1, 1);
            sum1 += __shfl_xor_sync(0xffffffffu, sum1, 2);
            lA[mi] = lA[mi] * al0 + sum0;
            lB[mi] = lB[mi] * al1 + sum1;
        }

        // O += P @ V : V B-frags via ldmatrix.trans from [kv][d] tile
#pragma unroll
        for (int kk = 0; kk < 4; kk++) {      // kv 16-chunks
            uint32_t pa[2][4];
#pragma unroll
            for (int mi = 0; mi < 2; mi++) {
                pa[mi][0] = pack2(s[mi][2 * kk][0],     s[mi][2 * kk][1]);
                pa[mi][1] = pack2(s[mi][2 * kk][2],     s[mi][2 * kk][3]);
                pa[mi][2] = pack2(s[mi][2 * kk + 1][0], s[mi][2 * kk + 1][1]);
                pa[mi][3] = pack2(s[mi][2 * kk + 1][2], s[mi][2 * kk + 1][3]);
            }
#pragma unroll
            for (int p = 0; p < 4; p++) {     // d 16-blocks
                uint32_t b0, b1, b2, b3;
                ldm_x4_trans(b0, b1, b2, b3,
                             v_addr + kk * (16 * GST * 2) + p * 32);
#pragma unroll
                for (int mi = 0; mi < 2; mi++) {
                    mma_fp16(o[mi][2 * p],     pa[mi][0], pa[mi][1], pa[mi][2], pa[mi][3], b0, b1);
                    mma_fp16(o[mi][2 * p + 1], pa[mi][0], pa[mi][1], pa[mi][2], pa[mi][3], b2, b3);
                }
            }
        }

        stg = (stg == 2) ? 0 : stg + 1;
        nstg = (nstg == 2) ? 0 : nstg + 1;
    }

    // epilogue: normalize, store fp16 to g_oh [B*T][C]
#pragma unroll
    for (int mi = 0; mi < 2; mi++) {
        const float inv0 = 1.0f / lA[mi];
        const float inv1 = 1.0f / lB[mi];
        const size_t r0 = (size_t)(b * NT + t0 + qbase + mi * 16 + g) * NC + h * HD;
        const size_t r1 = r0 + (size_t)8 * NC;
#pragma unroll
        for (int ni = 0; ni < 8; ni++) {
            const int col = ni * 8 + 2 * tg;
            *(uint32_t*)(g_oh + r0 + col) = pack2(o[mi][ni][0] * inv0, o[mi][ni][1] * inv0);
            *(uint32_t*)(g_oh + r1 + col) = pack2(o[mi][ni][2] * inv1, o[mi][ni][3] * inv1);
        }
    }
}

// ---------------- launch ------------------------------------------------------
extern "C" void kernel_launch(void* const* d_in, const int* in_sizes, int n_in,
                              void* d_out, int out_size)
{
    const float* x      = (const float*)d_in[0];
    const float* w_qkv  = (const float*)d_in[1];
    const float* b_qkv  = (const float*)d_in[2];
    const float* w_proj = (const float*)d_in[3];
    const float* b_proj = (const float*)d_in[4];
    float* out = (float*)d_out;

    __half *p_oh, *p_xh, *p_w1t, *p_w2t;
    cudaGetSymbolAddress((void**)&p_oh,  g_oh);
    cudaGetSymbolAddress((void**)&p_xh,  g_xh);
    cudaGetSymbolAddress((void**)&p_w1t, g_w1t);
    cudaGetSymbolAddress((void**)&p_w2t, g_w2t);

    const int gemm_smem  = 3 * GSTB;     // 110592 B
    const int flash_smem = 3 * FSTB;     // 55296 B
    cudaFuncSetAttribute(gemm_qkv_fused, cudaFuncAttributeMaxDynamicSharedMemorySize,
                         gemm_smem);
    cudaFuncSetAttribute(gemm_fp16, cudaFuncAttributeMaxDynamicSharedMemorySize,
                         gemm_smem);
    cudaFuncSetAttribute(flash_fp16, cudaFuncAttributeMaxDynamicSharedMemorySize,
                         flash_smem);

    // 0) prep: rope table; x -> fp16; weights -> transposed fp16 [N][K]
    rope_table<<<(NT * 32) / 256, 256>>>();
    round_half<<<(NM * NC) / 1024, 256>>>(x, p_xh);
    {
        dim3 grid(N3C / 32, NC / 32);
        transpose_round_h<<<grid, 256>>>(w_qkv, p_w1t, NC, N3C);
    }
    {
        dim3 grid(NC / 32, NC / 32);
        transpose_round_h<<<grid, 256>>>(w_proj, p_w2t, NC, NC);
    }

    // 1) fused qkv GEMM + bias + rope + split -> g_q/g_k/g_v fp16 [B,H,T,D]
    {
        dim3 grid(N3C / 128, NM / 128);
        gemm_qkv_fused<<<grid, 256, gemm_smem>>>(p_xh, p_w1t, b_qkv);
    }
    // 2) flash attention -> g_oh fp16
    {
        dim3 grid(NT / 128, NH, NB);
        flash_fp16<<<grid, 128, flash_smem>>>();
    }
    // 3) out = g_oh @ w_proj + b_proj
    {
        dim3 grid(NC / 128, NM / 128);
        gemm_fp16<<<grid, 256, gemm_smem>>>(p_oh, p_w2t, b_proj, out, NM, NC, NC);
    }
}